// round 12
// baseline (speedup 1.0000x reference)
#include <cuda_runtime.h>
#include <cuda_bf16.h>
#include <math.h>

// ---------------- constants ----------------
#define TPIF 6.283185307179586f
// output section offsets (floats)
#define OFF_Y    0
#define OFF_LAT  276480
#define OFF_SIG  291968
#define OFF_P    307456
#define OFF_FQ   307584
#define OFF_A    307712
#define OFF_B    307840
#define OFF_YP   307968

// ---------------- scratch ----------------
__device__ float  g_P[(size_t)16*24*121*240];   // S then k-prefix: [b][o][k][Q]
__device__ float  g_w2t[24*121*8 + 32];         // enc_w2 transposed [o][k][e] (+pad)
__device__ float4 g_twid4[121*64];              // (cs,cs,sn,sn) [t][f]
__device__ float  g_ys[(size_t)16*8*240*121];   // ysin [b][e][n][t]
__device__ float  g_scy[16*8*360];              // padded yc
__device__ float  g_dpre[16*24*240];            // dec conv1 pre-BN
__device__ float  g_bnm[24];
__device__ float  g_bni[24];
__device__ float  g_ddp[16*24*360];             // tanh(BN(d)) padded

#define FULLMASK 0xffffffffu
__device__ __forceinline__ float wred(float v) {
    v += __shfl_xor_sync(FULLMASK, v, 16);
    v += __shfl_xor_sync(FULLMASK, v, 8);
    v += __shfl_xor_sync(FULLMASK, v, 4);
    v += __shfl_xor_sync(FULLMASK, v, 2);
    v += __shfl_xor_sync(FULLMASK, v, 1);
    return v;
}

// packed f32x2 helpers
__device__ __forceinline__ unsigned long long dup2(float x) {
    unsigned long long r; unsigned u = __float_as_uint(x);
    asm("mov.b64 %0, {%1, %1};" : "=l"(r) : "r"(u));
    return r;
}
__device__ __forceinline__ void ffma2(unsigned long long& d, unsigned long long a, unsigned long long b) {
    asm("fma.rn.f32x2 %0, %1, %2, %0;" : "+l"(d) : "l"(a), "l"(b));
}
__device__ __forceinline__ float2 unpack2(unsigned long long v) {
    unsigned lo, hi;
    asm("mov.b64 {%0, %1}, %2;" : "=r"(lo), "=r"(hi) : "l"(v));
    return make_float2(__uint_as_float(lo), __uint_as_float(hi));
}

// ---------------- prep: twiddles + w2 transpose ----------------
__global__ void prep_k(const float* __restrict__ w2) {
    int i = blockIdx.x * blockDim.x + threadIdx.x;
    int stride = gridDim.x * blockDim.x;
    for (int idx = i; idx < 121 * 61; idx += stride) {
        int t = idx / 61, f = idx - 61 * t;
        float fr = (float)fmod((double)(2 * f * t) / 121.0, 2.0);
        float sn, cs; sincospif(fr, &sn, &cs);
        g_twid4[t * 64 + f] = make_float4(cs, cs, sn, sn);
    }
    for (int idx = i; idx < 24 * 121 * 8; idx += stride) {
        int e = idx & 7, ok = idx >> 3;
        int o = ok / 121, k = ok - 121 * o;
        g_w2t[idx] = w2[(e * 24 + o) * 121 + k];
    }
}

// ---------------- S[b,o,k,Q] ----------------
__global__ void __launch_bounds__(256) s_kernel(const float* __restrict__ x,
                                                const float* __restrict__ w1) {
    extern __shared__ float sm[];
    float* xs = sm;               // 72 x 244 (dup-padded)
    float* ws = sm + 72 * 244;    // 24 x 72
    const int k = blockIdx.x, b = blockIdx.y;
    const int tid = threadIdx.x;

    for (int idx = tid; idx < 72 * 240; idx += 256) {
        int i = idx / 240, c = idx - 240 * i;
        xs[i * 244 + c] = x[(b * 72 + i) * 240 + c];
    }
    for (int idx = tid; idx < 72 * 4; idx += 256) {
        int i = idx >> 2, j = idx & 3;
        xs[i * 244 + 240 + j] = x[(b * 72 + i) * 240 + j];
    }
    for (int idx = tid; idx < 24 * 72; idx += 256)
        ws[idx] = w1[idx * 121 + k];
    __syncthreads();

    for (int task = tid; task < 360; task += 256) {
        int og = task / 60, qg = task - 60 * og;
        int o0 = og * 4, Q0 = qg * 4;
        float acc[4][4];
        #pragma unroll
        for (int a = 0; a < 4; a++)
            #pragma unroll
            for (int q = 0; q < 4; q++) acc[a][q] = 0.f;
        int base = Q0 + k + 120; if (base >= 240) base -= 240;
        const float* xb = xs + base;
        const float* wp0 = ws + (o0 + 0) * 72;
        const float* wp1 = ws + (o0 + 1) * 72;
        const float* wp2 = ws + (o0 + 2) * 72;
        const float* wp3 = ws + (o0 + 3) * 72;
        #pragma unroll 4
        for (int i = 0; i < 72; i++) {
            const float* xr = xb + i * 244;
            float x0 = xr[0], x1 = xr[1], x2 = xr[2], x3 = xr[3];
            float w0 = wp0[i], w1v = wp1[i], w2v = wp2[i], w3v = wp3[i];
            acc[0][0]=fmaf(w0,x0,acc[0][0]); acc[0][1]=fmaf(w0,x1,acc[0][1]);
            acc[0][2]=fmaf(w0,x2,acc[0][2]); acc[0][3]=fmaf(w0,x3,acc[0][3]);
            acc[1][0]=fmaf(w1v,x0,acc[1][0]); acc[1][1]=fmaf(w1v,x1,acc[1][1]);
            acc[1][2]=fmaf(w1v,x2,acc[1][2]); acc[1][3]=fmaf(w1v,x3,acc[1][3]);
            acc[2][0]=fmaf(w2v,x0,acc[2][0]); acc[2][1]=fmaf(w2v,x1,acc[2][1]);
            acc[2][2]=fmaf(w2v,x2,acc[2][2]); acc[2][3]=fmaf(w2v,x3,acc[2][3]);
            acc[3][0]=fmaf(w3v,x0,acc[3][0]); acc[3][1]=fmaf(w3v,x1,acc[3][1]);
            acc[3][2]=fmaf(w3v,x2,acc[3][2]); acc[3][3]=fmaf(w3v,x3,acc[3][3]);
        }
        size_t pbase = ((size_t)(b * 24 + o0) * 121 + k) * 240 + Q0;
        #pragma unroll
        for (int oo = 0; oo < 4; oo++)
            #pragma unroll
            for (int qq = 0; qq < 4; qq++)
                g_P[pbase + (size_t)oo * 121 * 240 + qq] = acc[oo][qq];
    }
}

// ---------------- prefix over k ----------------
__global__ void prefix_k() {
    int bo = blockIdx.x, Q = threadIdx.x;
    if (Q < 240) {
        size_t base = (size_t)bo * 121 * 240 + Q;
        float acc = 0.f;
        for (int k = 0; k < 121; k++) {
            acc += g_P[base + (size_t)k * 240];
            g_P[base + (size_t)k * 240] = acc;
        }
    }
}

// 16 packed FMAs for one k: 2 e-pairs (w.x, w.y) x 4 t's x 2 windows
#define K16(w, h0, h1, h2, h3, q0, q1, q2, q3) \
    ffma2(A00, w.x, h0); ffma2(A01, w.x, h1); ffma2(A02, w.x, h2); ffma2(A03, w.x, h3); \
    ffma2(A10, w.y, h0); ffma2(A11, w.y, h1); ffma2(A12, w.y, h2); ffma2(A13, w.y, h3); \
    ffma2(B00, w.x, q0); ffma2(B01, w.x, q1); ffma2(B02, w.x, q2); ffma2(B03, w.x, q3); \
    ffma2(B10, w.y, q0); ffma2(B11, w.y, q1); ffma2(B12, w.y, q2); ffma2(B13, w.y, q3);

// ---------------- encoder v4: warp = 2 windows x 4 e's ----------------
// block = 128 thr = 4 warps = 2 window-pairs (each pair served by 2 e-half warps).
// smem: 4 window slots x 6048 floats (hp 24x252; lt overlays hp[0..976) after sync).
__global__ void __launch_bounds__(128, 2) encode_k(
    const float* __restrict__ lna, const float* __restrict__ lnb,
    const float* __restrict__ b2, const float* __restrict__ fcw,
    const float* __restrict__ fcb, float* __restrict__ out)
{
    extern __shared__ float sm[];
    const int warp = threadIdx.x >> 5, lane = threadIdx.x & 31;
    const int wpair = warp >> 1, ehalf = warp & 1;
    const int W = blockIdx.x * 2 + wpair;       // window pair id
    const int s0 = 2 * W;                       // windows s0, s0+1 (same batch: 240 even)
    const int b = s0 / 240, n0 = s0 - b * 240;
    float* hp0 = sm + (wpair * 2 + 0) * 6048;
    float* hp1 = sm + (wpair * 2 + 1) * 6048;

    for (int i = threadIdx.x; i < 4 * 6048; i += 128) sm[i] = 0.f;
    __syncthreads();

    // ---- conv1 via prefix diffs + LayerNorm + tanh: 2 windows x 12 o's per warp ----
    const size_t pb0 = (size_t)(b * 24) * 121 * 240;
    for (int widx = 0; widx < 2; widx++) {
        float* hpw = widx ? hp1 : hp0;
        int n = n0 + widx;
        for (int oo = 0; oo < 12; oo++) {
            int o = ehalf * 12 + oo;
            const float* P = g_P + pb0 + (size_t)o * 121 * 240;
            float hv[4]; float s1 = 0.f, s2 = 0.f;
            #pragma unroll
            for (int j = 0; j < 4; j++) {
                int t = lane + 32 * j;
                float h = 0.f;
                if (t < 121) {
                    int Q = n + t; if (Q >= 240) Q -= 240;
                    if (t < 60) h = P[120 * 240 + Q] - P[(59 - t) * 240 + Q];
                    else        h = P[(180 - t) * 240 + Q];
                    s1 += h; s2 += h * h;
                }
                hv[j] = h;
            }
            s1 = wred(s1); s2 = wred(s2);
            float mean = s1 * (1.f / 121.f);
            float var = (s2 - s1 * mean) * (1.f / 120.f);
            float inv = 1.f / (sqrtf(var) + 1e-5f);
            #pragma unroll
            for (int j = 0; j < 4; j++) {
                int t = lane + 32 * j;
                if (t < 121)
                    hpw[o * 252 + 60 + t] = tanhf((hv[j] - mean) * inv * lna[t] + lnb[t]);
            }
        }
    }
    __syncthreads();

    // ---- conv2: 2 windows x 2 e-pairs x 4 t's per lane, weights shared across windows ----
    const int ebase = ehalf * 4;
    const int t0 = 4 * lane;
    unsigned long long A00=0,A01=0,A02=0,A03=0,A10=0,A11=0,A12=0,A13=0;
    unsigned long long B00=0,B01=0,B02=0,B03=0,B10=0,B11=0,B12=0,B13=0;

    for (int o = 0; o < 24; o++) {
        const float* hr0 = hp0 + o * 252 + t0;
        const float* hr1 = hp1 + o * 252 + t0;
        const ulonglong2* wp = (const ulonglong2*)(g_w2t + o * 968 + ebase);
        float4 c0 = *(const float4*)hr0;
        float4 c1 = *(const float4*)hr1;
        unsigned long long d0 = dup2(c0.x), d1 = dup2(c0.y), d2 = dup2(c0.z), d3 = dup2(c0.w);
        unsigned long long f0 = dup2(c1.x), f1 = dup2(c1.y), f2 = dup2(c1.z), f3 = dup2(c1.w);
        #pragma unroll 2
        for (int g = 0; g < 30; g++) {
            float4 n0v = *(const float4*)(hr0 + 4 * g + 4);
            float4 n1v = *(const float4*)(hr1 + 4 * g + 4);
            ulonglong2 wA = wp[8 * g + 0], wB = wp[8 * g + 2],
                       wC = wp[8 * g + 4], wD = wp[8 * g + 6];
            unsigned long long e0 = dup2(n0v.x), e1 = dup2(n0v.y),
                               e2 = dup2(n0v.z), e3 = dup2(n0v.w);
            unsigned long long g0 = dup2(n1v.x), g1 = dup2(n1v.y),
                               g2 = dup2(n1v.z), g3 = dup2(n1v.w);
            K16(wA, d0, d1, d2, d3,  f0, f1, f2, f3)
            K16(wB, d1, d2, d3, e0,  f1, f2, f3, g0)
            K16(wC, d2, d3, e0, e1,  f2, f3, g0, g1)
            K16(wD, d3, e0, e1, e2,  f3, g0, g1, g2)
            d0 = e0; d1 = e1; d2 = e2; d3 = e3;
            f0 = g0; f1 = g1; f2 = g2; f3 = g3;
        }
        {   // k = 120
            ulonglong2 wE = wp[240];
            K16(wE, d0, d1, d2, d3,  f0, f1, f2, f3)
        }
    }

    // hp dead for everyone after this barrier; overlay lt into slot base
    __syncthreads();

    float* lt0 = hp0;  // lt[t*8 + e], 976 floats
    float* lt1 = hp1;
    {
        float be0 = b2[ebase], be1 = b2[ebase + 1];
        float be2 = b2[ebase + 2], be3 = b2[ebase + 3];
        unsigned long long a0[4] = {A00, A01, A02, A03};
        unsigned long long a1[4] = {A10, A11, A12, A13};
        unsigned long long b0[4] = {B00, B01, B02, B03};
        unsigned long long b1[4] = {B10, B11, B12, B13};
        #pragma unroll
        for (int j = 0; j < 4; j++) {
            int t = t0 + j;
            if (t < 121) {
                float2 v = unpack2(a0[j]), u = unpack2(a1[j]);
                *(float2*)&lt0[t * 8 + ebase]     = make_float2(v.x + be0, v.y + be1);
                *(float2*)&lt0[t * 8 + ebase + 2] = make_float2(u.x + be2, u.y + be3);
                float2 p = unpack2(b0[j]), q = unpack2(b1[j]);
                *(float2*)&lt1[t * 8 + ebase]     = make_float2(p.x + be0, p.y + be1);
                *(float2*)&lt1[t * 8 + ebase + 2] = make_float2(q.x + be2, q.y + be3);
            }
        }
    }
    __syncwarp();

    // ---- per-window epilogue: DFT + fc + params + outputs + resynthesis ----
    for (int widx = 0; widx < 2; widx++) {
        float* lt = widx ? lt1 : lt0;
        int n = n0 + widx;

        float num[4] = {0.f,0.f,0.f,0.f}, den[4] = {0.f,0.f,0.f,0.f};
        #pragma unroll
        for (int round = 0; round < 2; round++) {
            int fi = lane + 32 * round;
            if (fi < 60) {
                unsigned long long cr01=0, cr23=0, ci01=0, ci23=0;
                const ulonglong2* tw = (const ulonglong2*)g_twid4 + fi + 1;
                const float* ltb = lt + ebase;
                for (int t = 0; t < 121; t++) {
                    ulonglong2 w2v = tw[t * 64];
                    ulonglong2 l   = *(const ulonglong2*)(ltb + t * 8);
                    ffma2(cr01, w2v.x, l.x); ffma2(cr23, w2v.x, l.y);
                    ffma2(ci01, w2v.y, l.x); ffma2(ci23, w2v.y, l.y);
                }
                float2 c01 = unpack2(cr01), c23 = unpack2(cr23);
                float2 s01 = unpack2(ci01), s23 = unpack2(ci23);
                float cr[4] = {c01.x, c01.y, c23.x, c23.y};
                float ci[4] = {s01.x, s01.y, s23.x, s23.y};
                float fr = 0.5f * (float)(fi + 1);
                #pragma unroll
                for (int e = 0; e < 4; e++) {
                    float pw = cr[e] * cr[e] + ci[e] * ci[e];
                    num[e] = fmaf(pw, fr, num[e]);
                    den[e] += pw;
                }
            }
        }
        #pragma unroll
        for (int e = 0; e < 4; e++) { num[e] = wred(num[e]); den[e] = wred(den[e]); }

        float sb[4] = {0.f,0.f,0.f,0.f}, sv0[4] = {0.f,0.f,0.f,0.f}, sv1[4] = {0.f,0.f,0.f,0.f};
        #pragma unroll
        for (int j = 0; j < 4; j++) {
            int t = lane + 32 * j;
            if (t < 121) {
                float4 l4 = *(const float4*)(lt + t * 8 + ebase);
                float le[4] = {l4.x, l4.y, l4.z, l4.w};
                #pragma unroll
                for (int e = 0; e < 4; e++) {
                    int eg = ebase + e;
                    sb[e] += le[e];
                    sv0[e] = fmaf(le[e], fcw[(eg * 2 + 0) * 121 + t], sv0[e]);
                    sv1[e] = fmaf(le[e], fcw[(eg * 2 + 1) * 121 + t], sv1[e]);
                }
            }
        }
        float bo_[4], v0[4], v1[4];
        #pragma unroll
        for (int e = 0; e < 4; e++) {
            int eg = ebase + e;
            bo_[e] = wred(sb[e]) * (1.f / 121.f);
            v0[e] = wred(sv0[e]) + fcb[eg * 2];
            v1[e] = wred(sv1[e]) + fcb[eg * 2 + 1];
        }

        float fe[4], am[4], ph[4];
        #pragma unroll
        for (int e = 0; e < 4; e++) {
            fe[e] = num[e] / den[e];
            am[e] = 2.f * sqrtf(den[e]) * (1.f / 121.f);
            ph[e] = atan2f(v1[e], v0[e]);
        }

        if (n == 0) {
            if (lane == 0) {
                #pragma unroll
                for (int e = 0; e < 4; e++) {
                    int eg = ebase + e;
                    out[OFF_P  + b * 8 + eg] = ph[e] * (1.f / TPIF);
                    out[OFF_FQ + b * 8 + eg] = fe[e];
                    out[OFF_A  + b * 8 + eg] = am[e];
                    out[OFF_B  + b * 8 + eg] = bo_[e];
                }
            }
            #pragma unroll
            for (int e = 0; e < 4; e++) {
                int eg = ebase + e;
                for (int t = lane; t < 121; t += 32)
                    out[OFF_LAT + (b * 8 + eg) * 121 + t] = lt[t * 8 + eg];
            }
        }

        #pragma unroll
        for (int e = 0; e < 4; e++) {
            int eg = ebase + e;
            float* yd = g_ys + ((size_t)(b * 8 + eg) * 240 + n) * 121;
            float w = TPIF * fe[e];
            for (int t = lane; t < 121; t += 32) {
                float arg = fmaf(w, (float)(t - 60) * (1.f / 60.f), ph[e]);
                yd[t] = fmaf(am[e], sinf(arg), bo_[e]);
            }
        }
    }
}

// ---------------- overlap-add (deterministic gather) ----------------
__global__ void overlap_k(float* __restrict__ out) {
    int be = blockIdx.x;
    int j = threadIdx.x; // 0..359
    const float* ys = g_ys + (size_t)be * 240 * 121;
    int tlo = j - 239; if (tlo < 0) tlo = 0;
    int thi = j < 120 ? j : 120;
    float s = 0.f;
    for (int t = tlo; t <= thi; t++) s += ys[(j - t) * 121 + t];
    float w = (j < 121) ? (float)(j + 1) : (j > 239 ? (float)(360 - j) : 121.f);
    float sig = s / w;
    if (j < 121) out[OFF_SIG + be * 121 + j] = sig;
    g_scy[be * 360 + j] = (j >= 60 && j < 300) ? sig : 0.f;
}

// ---------------- decoder conv1 (bias skipped: cancels in BN) ----------------
__global__ void __launch_bounds__(256) dec1_k(const float* __restrict__ dw1) {
    __shared__ float ys[8 * 360], ws[8 * 121];
    int b = blockIdx.x, o = blockIdx.y, tid = threadIdx.x;
    for (int i = tid; i < 8 * 360; i += 256)
        ys[i] = g_scy[(b * 8 + i / 360) * 360 + i % 360];
    for (int i = tid; i < 8 * 121; i += 256)
        ws[i] = dw1[o * 8 * 121 + i];
    __syncthreads();
    if (tid < 240) {
        float acc = 0.f;
        #pragma unroll
        for (int e = 0; e < 8; e++) {
            const float* yr = ys + e * 360 + tid;
            const float* wr = ws + e * 121;
            #pragma unroll 4
            for (int k = 0; k < 121; k++) acc = fmaf(wr[k], yr[k], acc);
        }
        g_dpre[(b * 24 + o) * 240 + tid] = acc;
    }
}

// ---------------- BN stats (deterministic tree) ----------------
__global__ void bnstat_k() {
    __shared__ float r1[256], r2[256];
    int o = blockIdx.x, tid = threadIdx.x;
    float s1 = 0.f, s2 = 0.f;
    for (int i = tid; i < 3840; i += 256) {
        int bb = i / 240, t = i - 240 * bb;
        float v = g_dpre[(bb * 24 + o) * 240 + t];
        s1 += v; s2 += v * v;
    }
    r1[tid] = s1; r2[tid] = s2; __syncthreads();
    for (int st = 128; st > 0; st >>= 1) {
        if (tid < st) { r1[tid] += r1[tid + st]; r2[tid] += r2[tid + st]; }
        __syncthreads();
    }
    if (tid == 0) {
        float m = r1[0] * (1.f / 3840.f);
        g_bnm[o] = m;
        g_bni[o] = rsqrtf(r2[0] * (1.f / 3840.f) - m * m + 1e-5f);
    }
}

__global__ void bnapply_k(const float* __restrict__ gam, const float* __restrict__ bet) {
    int idx = blockIdx.x * blockDim.x + threadIdx.x;
    if (idx >= 16 * 24 * 360) return;
    int tau = idx % 360, bo = idx / 360;
    int o = bo % 24;
    float v = 0.f;
    if (tau >= 60 && tau < 300)
        v = tanhf((g_dpre[bo * 240 + tau - 60] - g_bnm[o]) * g_bni[o] * gam[o] + bet[o]);
    g_ddp[idx] = v;
}

// ---------------- decoder conv2 + outputs ----------------
__global__ void __launch_bounds__(64) dec2_k(const float* __restrict__ dw2,
                                             const float* __restrict__ db2,
                                             float* __restrict__ out) {
    __shared__ float dd[24 * 360], ws[24 * 121];
    int b = blockIdx.x, c = blockIdx.y, tid = threadIdx.x;
    for (int i = tid; i < 24 * 360; i += 64) dd[i] = g_ddp[b * 24 * 360 + i];
    for (int i = tid; i < 24 * 121; i += 64) ws[i] = dw2[c * 24 * 121 + i];
    __syncthreads();
    if (tid < 60) {
        int t0 = tid * 4;
        float a0 = 0.f, a1 = 0.f, a2 = 0.f, a3 = 0.f;
        for (int o = 0; o < 24; o++) {
            const float* dr = dd + o * 360 + t0;
            const float* wr = ws + o * 121;
            float x0 = dr[0], x1 = dr[1], x2 = dr[2];
            #pragma unroll 4
            for (int k = 0; k < 121; k++) {
                float w = wr[k]; float x3 = dr[k + 3];
                a0 = fmaf(w, x0, a0); a1 = fmaf(w, x1, a1);
                a2 = fmaf(w, x2, a2); a3 = fmaf(w, x3, a3);
                x0 = x1; x1 = x2; x2 = x3;
            }
        }
        float bias = db2[c];
        float r[4] = { a0 + bias, a1 + bias, a2 + bias, a3 + bias };
        size_t yb = (size_t)(b * 72 + c) * 240 + t0;
        #pragma unroll
        for (int q = 0; q < 4; q++) {
            out[OFF_Y + yb + q] = r[q];
            int t = t0 + q;
            if (t < 121) out[OFF_YP + (b * 72 + c) * 121 + t] = r[q];
        }
    }
}

// ---------------- launch ----------------
extern "C" void kernel_launch(void* const* d_in, const int* in_sizes, int n_in,
                              void* d_out, int out_size) {
    const float* x   = (const float*)d_in[0];
    const float* w1  = (const float*)d_in[1];
    const float* lna = (const float*)d_in[3];
    const float* lnb = (const float*)d_in[4];
    const float* w2  = (const float*)d_in[5];
    const float* b2  = (const float*)d_in[6];
    const float* fcw = (const float*)d_in[7];
    const float* fcb = (const float*)d_in[8];
    const float* dw1 = (const float*)d_in[9];
    const float* bng = (const float*)d_in[11];
    const float* bnb = (const float*)d_in[12];
    const float* dw2 = (const float*)d_in[13];
    const float* db2 = (const float*)d_in[14];
    float* out = (float*)d_out;

    const int SMEM_S = (72 * 244 + 24 * 72) * 4;      // 77184
    const int SMEM_E = 4 * 6048 * 4;                  // 96768
    cudaFuncSetAttribute(s_kernel, cudaFuncAttributeMaxDynamicSharedMemorySize, SMEM_S);
    cudaFuncSetAttribute(encode_k, cudaFuncAttributeMaxDynamicSharedMemorySize, SMEM_E);

    prep_k<<<64, 256>>>(w2);
    s_kernel<<<dim3(121, 16), 256, SMEM_S>>>(x, w1);
    prefix_k<<<384, 256>>>();
    encode_k<<<960, 128, SMEM_E>>>(lna, lnb, b2, fcw, fcb, out);
    overlap_k<<<128, 360>>>(out);
    dec1_k<<<dim3(16, 24), 256>>>(dw1);
    bnstat_k<<<24, 256>>>();
    bnapply_k<<<540, 256>>>(bng, bnb);
    dec2_k<<<dim3(16, 72), 64>>>(dw2, db2, out);
}

// round 14
// speedup vs baseline: 1.0485x; 1.0485x over previous
#include <cuda_runtime.h>
#include <cuda_bf16.h>
#include <math.h>

// ---------------- constants ----------------
#define TPIF 6.283185307179586f
#define OFF_Y    0
#define OFF_LAT  276480
#define OFF_SIG  291968
#define OFF_P    307456
#define OFF_FQ   307584
#define OFF_A    307712
#define OFF_B    307840
#define OFF_YP   307968

// ---------------- scratch ----------------
__device__ float  g_P[(size_t)16*24*121*240];            // S then k-prefix: [b][o][k][Q]
__device__ __align__(16) float g_w2t[24*121*8 + 64];     // enc_w2 transposed [o][k][e] (+pad)
__device__ float4 g_twid4[121*64];                       // (cs,cs,sn,sn) [t][f]
__device__ float  g_ys[(size_t)16*8*240*121];            // ysin [b][e][n][t]
__device__ float  g_scy[16*8*360];                       // padded yc
__device__ float  g_dpre[16*24*240];                     // dec conv1 pre-BN
__device__ float  g_bnm[24];
__device__ float  g_bni[24];
__device__ float  g_ddp[16*24*360];                      // tanh(BN(d)) padded

#define FULLMASK 0xffffffffu
__device__ __forceinline__ float wred(float v) {
    v += __shfl_xor_sync(FULLMASK, v, 16);
    v += __shfl_xor_sync(FULLMASK, v, 8);
    v += __shfl_xor_sync(FULLMASK, v, 4);
    v += __shfl_xor_sync(FULLMASK, v, 2);
    v += __shfl_xor_sync(FULLMASK, v, 1);
    return v;
}

// packed f32x2 helpers
__device__ __forceinline__ unsigned long long dup2(float x) {
    unsigned long long r; unsigned u = __float_as_uint(x);
    asm("mov.b64 %0, {%1, %1};" : "=l"(r) : "r"(u));
    return r;
}
__device__ __forceinline__ void ffma2(unsigned long long& d, unsigned long long a, unsigned long long b) {
    asm("fma.rn.f32x2 %0, %1, %2, %0;" : "+l"(d) : "l"(a), "l"(b));
}
__device__ __forceinline__ float2 unpack2(unsigned long long v) {
    unsigned lo, hi;
    asm("mov.b64 {%0, %1}, %2;" : "=r"(lo), "=r"(hi) : "l"(v));
    return make_float2(__uint_as_float(lo), __uint_as_float(hi));
}

// ---------------- prep: twiddles + w2 transpose ----------------
__global__ void prep_k(const float* __restrict__ w2) {
    int i = blockIdx.x * blockDim.x + threadIdx.x;
    int stride = gridDim.x * blockDim.x;
    for (int idx = i; idx < 121 * 61; idx += stride) {
        int t = idx / 61, f = idx - 61 * t;
        float fr = (float)fmod((double)(2 * f * t) / 121.0, 2.0);
        float sn, cs; sincospif(fr, &sn, &cs);
        g_twid4[t * 64 + f] = make_float4(cs, cs, sn, sn);
    }
    for (int idx = i; idx < 24 * 121 * 8; idx += stride) {
        int e = idx & 7, ok = idx >> 3;
        int o = ok / 121, k = ok - 121 * o;
        g_w2t[idx] = w2[(e * 24 + o) * 121 + k];
    }
    for (int idx = i; idx < 64; idx += stride) g_w2t[24 * 121 * 8 + idx] = 0.f;
}

// ---------------- S[b,o,k,Q] ----------------
__global__ void __launch_bounds__(256) s_kernel(const float* __restrict__ x,
                                                const float* __restrict__ w1) {
    extern __shared__ float sm[];
    float* xs = sm;               // 72 x 244 (dup-padded)
    float* ws = sm + 72 * 244;    // 24 x 72
    const int k = blockIdx.x, b = blockIdx.y;
    const int tid = threadIdx.x;

    for (int idx = tid; idx < 72 * 240; idx += 256) {
        int i = idx / 240, c = idx - 240 * i;
        xs[i * 244 + c] = x[(b * 72 + i) * 240 + c];
    }
    for (int idx = tid; idx < 72 * 4; idx += 256) {
        int i = idx >> 2, j = idx & 3;
        xs[i * 244 + 240 + j] = x[(b * 72 + i) * 240 + j];
    }
    for (int idx = tid; idx < 24 * 72; idx += 256)
        ws[idx] = w1[idx * 121 + k];
    __syncthreads();

    for (int task = tid; task < 360; task += 256) {
        int og = task / 60, qg = task - 60 * og;
        int o0 = og * 4, Q0 = qg * 4;
        float acc[4][4];
        #pragma unroll
        for (int a = 0; a < 4; a++)
            #pragma unroll
            for (int q = 0; q < 4; q++) acc[a][q] = 0.f;
        int base = Q0 + k + 120; if (base >= 240) base -= 240;
        const float* xb = xs + base;
        const float* wp0 = ws + (o0 + 0) * 72;
        const float* wp1 = ws + (o0 + 1) * 72;
        const float* wp2 = ws + (o0 + 2) * 72;
        const float* wp3 = ws + (o0 + 3) * 72;
        #pragma unroll 4
        for (int i = 0; i < 72; i++) {
            const float* xr = xb + i * 244;
            float x0 = xr[0], x1 = xr[1], x2 = xr[2], x3 = xr[3];
            float w0 = wp0[i], w1v = wp1[i], w2v = wp2[i], w3v = wp3[i];
            acc[0][0]=fmaf(w0,x0,acc[0][0]); acc[0][1]=fmaf(w0,x1,acc[0][1]);
            acc[0][2]=fmaf(w0,x2,acc[0][2]); acc[0][3]=fmaf(w0,x3,acc[0][3]);
            acc[1][0]=fmaf(w1v,x0,acc[1][0]); acc[1][1]=fmaf(w1v,x1,acc[1][1]);
            acc[1][2]=fmaf(w1v,x2,acc[1][2]); acc[1][3]=fmaf(w1v,x3,acc[1][3]);
            acc[2][0]=fmaf(w2v,x0,acc[2][0]); acc[2][1]=fmaf(w2v,x1,acc[2][1]);
            acc[2][2]=fmaf(w2v,x2,acc[2][2]); acc[2][3]=fmaf(w2v,x3,acc[2][3]);
            acc[3][0]=fmaf(w3v,x0,acc[3][0]); acc[3][1]=fmaf(w3v,x1,acc[3][1]);
            acc[3][2]=fmaf(w3v,x2,acc[3][2]); acc[3][3]=fmaf(w3v,x3,acc[3][3]);
        }
        size_t pbase = ((size_t)(b * 24 + o0) * 121 + k) * 240 + Q0;
        #pragma unroll
        for (int oo = 0; oo < 4; oo++)
            #pragma unroll
            for (int qq = 0; qq < 4; qq++)
                g_P[pbase + (size_t)oo * 121 * 240 + qq] = acc[oo][qq];
    }
}

// ---------------- prefix over k ----------------
__global__ void prefix_k() {
    int bo = blockIdx.x, Q = threadIdx.x;
    if (Q < 240) {
        size_t base = (size_t)bo * 121 * 240 + Q;
        float acc = 0.f;
        for (int k = 0; k < 121; k++) {
            acc += g_P[base + (size_t)k * 240];
            g_P[base + (size_t)k * 240] = acc;
        }
    }
}

// 16 packed FMAs for one k: 2 e-pairs (w.x, w.y) x 4 t's x 2 windows
#define K16(w, h0, h1, h2, h3, q0, q1, q2, q3) \
    ffma2(A00, w.x, h0); ffma2(A01, w.x, h1); ffma2(A02, w.x, h2); ffma2(A03, w.x, h3); \
    ffma2(A10, w.y, h0); ffma2(A11, w.y, h1); ffma2(A12, w.y, h2); ffma2(A13, w.y, h3); \
    ffma2(B00, w.x, q0); ffma2(B01, w.x, q1); ffma2(B02, w.x, q2); ffma2(B03, w.x, q3); \
    ffma2(B10, w.y, q0); ffma2(B11, w.y, q1); ffma2(B12, w.y, q2); ffma2(B13, w.y, q3);

// ---------------- encoder v6: 2 windows/warp, unpadded fp32 h + zero-row redirect ----
// block = 128 thr = 4 warps = (wpair, ehalf); 4 windows/block.
// slot = 3200 floats: hp 24 rows x 128 (cols 121..127 zero) + zero row at [3072..3200).
// lt (float, 976) overlays slot base after conv2.
__global__ void __launch_bounds__(128, 4) encode_k(
    const float* __restrict__ lna, const float* __restrict__ lnb,
    const float* __restrict__ b2, const float* __restrict__ fcw,
    const float* __restrict__ fcb, float* __restrict__ out)
{
    extern __shared__ float sm[];
    const int warp = threadIdx.x >> 5, lane = threadIdx.x & 31;
    const int wpair = warp >> 1, ehalf = warp & 1;
    const int s0 = blockIdx.x * 4 + wpair * 2;        // windows s0, s0+1
    const int b = s0 / 240, n0 = s0 - b * 240;        // 240 % 4 == 0 -> same b
    float* hp0 = sm + (wpair * 2 + 0) * 3200;
    float* hp1 = sm + (wpair * 2 + 1) * 3200;

    for (int i = threadIdx.x; i < 4 * 3200; i += 128) sm[i] = 0.f;
    __syncthreads();

    // ---- conv1 via prefix diffs + LayerNorm + tanh: 2 windows x 12 o's per warp ----
    const size_t pb0 = (size_t)(b * 24) * 121 * 240;
    for (int widx = 0; widx < 2; widx++) {
        float* hpw = widx ? hp1 : hp0;
        int n = n0 + widx;
        for (int oo = 0; oo < 12; oo++) {
            int o = ehalf * 12 + oo;
            const float* P = g_P + pb0 + (size_t)o * 121 * 240;
            float hv[4]; float s1 = 0.f, s2 = 0.f;
            #pragma unroll
            for (int j = 0; j < 4; j++) {
                int t = lane + 32 * j;
                float h = 0.f;
                if (t < 121) {
                    int Q = n + t; if (Q >= 240) Q -= 240;
                    if (t < 60) h = P[120 * 240 + Q] - P[(59 - t) * 240 + Q];
                    else        h = P[(180 - t) * 240 + Q];
                    s1 += h; s2 += h * h;
                }
                hv[j] = h;
            }
            s1 = wred(s1); s2 = wred(s2);
            float mean = s1 * (1.f / 121.f);
            float var = (s2 - s1 * mean) * (1.f / 120.f);
            float inv = 1.f / (sqrtf(var) + 1e-5f);
            #pragma unroll
            for (int j = 0; j < 4; j++) {
                int t = lane + 32 * j;
                if (t < 121)
                    hpw[o * 128 + t] = tanhf((hv[j] - mean) * inv * lna[t] + lnb[t]);
            }
        }
    }
    __syncthreads();

    // ---- conv2: 2 windows x 2 e-pairs x 4 t's per lane ----
    const int ebase = ehalf * 4;
    unsigned long long A00=0,A01=0,A02=0,A03=0,A10=0,A11=0,A12=0,A13=0;
    unsigned long long B00=0,B01=0,B02=0,B03=0,B10=0,B11=0,B12=0,B13=0;

    for (int o = 0; o < 24; o++) {
        const int rowoff = o * 128;
        const ulonglong2* wp = (const ulonglong2*)(g_w2t + o * 968 + ebase);
        // initial cur: float4 index jj = lane-15 (valid 0..30, else zero row)
        int off0 = ((unsigned)(lane - 15) <= 30u) ? rowoff + 4 * (lane - 15) : 3072;
        float4 c0 = *(const float4*)(hp0 + off0);
        float4 c1 = *(const float4*)(hp1 + off0);
        unsigned long long d0 = dup2(c0.x), d1 = dup2(c0.y), d2 = dup2(c0.z), d3 = dup2(c0.w);
        unsigned long long f0 = dup2(c1.x), f1 = dup2(c1.y), f2 = dup2(c1.z), f3 = dup2(c1.w);
        #pragma unroll 1
        for (int g = 0; g < 30; g++) {
            int jj = lane + g - 14;   // next float4 index
            int offn = ((unsigned)jj <= 30u) ? rowoff + 4 * jj : 3072;
            float4 n0v = *(const float4*)(hp0 + offn);
            float4 n1v = *(const float4*)(hp1 + offn);
            ulonglong2 wA = wp[8 * g + 0], wB = wp[8 * g + 2],
                       wC = wp[8 * g + 4], wD = wp[8 * g + 6];
            unsigned long long e0 = dup2(n0v.x), e1 = dup2(n0v.y),
                               e2 = dup2(n0v.z), e3 = dup2(n0v.w);
            unsigned long long g0 = dup2(n1v.x), g1 = dup2(n1v.y),
                               g2 = dup2(n1v.z), g3 = dup2(n1v.w);
            K16(wA, d0, d1, d2, d3,  f0, f1, f2, f3)
            K16(wB, d1, d2, d3, e0,  f1, f2, f3, g0)
            K16(wC, d2, d3, e0, e1,  f2, f3, g0, g1)
            K16(wD, d3, e0, e1, e2,  f3, g0, g1, g2)
            d0 = e0; d1 = e1; d2 = e2; d3 = e3;
            f0 = g0; f1 = g1; f2 = g2; f3 = g3;
        }
        {   // k = 120
            ulonglong2 wE = wp[240];
            K16(wE, d0, d1, d2, d3,  f0, f1, f2, f3)
        }
    }

    // hp dead for everyone after this barrier; overlay lt into slot base
    __syncthreads();

    float* lt0 = hp0;  // lt[t*8 + e], 976 floats
    float* lt1 = hp1;
    const int t0 = 4 * lane;
    {
        float be0 = b2[ebase], be1 = b2[ebase + 1];
        float be2 = b2[ebase + 2], be3 = b2[ebase + 3];
        unsigned long long a0[4] = {A00, A01, A02, A03};
        unsigned long long a1[4] = {A10, A11, A12, A13};
        unsigned long long b0[4] = {B00, B01, B02, B03};
        unsigned long long b1[4] = {B10, B11, B12, B13};
        #pragma unroll
        for (int j = 0; j < 4; j++) {
            int t = t0 + j;
            if (t < 121) {
                float2 v = unpack2(a0[j]), u = unpack2(a1[j]);
                *(float2*)&lt0[t * 8 + ebase]     = make_float2(v.x + be0, v.y + be1);
                *(float2*)&lt0[t * 8 + ebase + 2] = make_float2(u.x + be2, u.y + be3);
                float2 p = unpack2(b0[j]), q = unpack2(b1[j]);
                *(float2*)&lt1[t * 8 + ebase]     = make_float2(p.x + be0, p.y + be1);
                *(float2*)&lt1[t * 8 + ebase + 2] = make_float2(q.x + be2, q.y + be3);
            }
        }
    }
    __syncwarp();

    // ---- per-window epilogue: DFT + fc + params + outputs + resynthesis ----
    for (int widx = 0; widx < 2; widx++) {
        float* lt = widx ? lt1 : lt0;
        int n = n0 + widx;

        float num[4] = {0.f,0.f,0.f,0.f}, den[4] = {0.f,0.f,0.f,0.f};
        #pragma unroll
        for (int round = 0; round < 2; round++) {
            int fi = lane + 32 * round;
            if (fi < 60) {
                unsigned long long cr01=0, cr23=0, ci01=0, ci23=0;
                const ulonglong2* tw = (const ulonglong2*)g_twid4 + fi + 1;
                const float* ltb = lt + ebase;
                for (int t = 0; t < 121; t++) {
                    ulonglong2 w2v = tw[t * 64];
                    ulonglong2 l   = *(const ulonglong2*)(ltb + t * 8);
                    ffma2(cr01, w2v.x, l.x); ffma2(cr23, w2v.x, l.y);
                    ffma2(ci01, w2v.y, l.x); ffma2(ci23, w2v.y, l.y);
                }
                float2 c01 = unpack2(cr01), c23 = unpack2(cr23);
                float2 s01 = unpack2(ci01), s23 = unpack2(ci23);
                float cr[4] = {c01.x, c01.y, c23.x, c23.y};
                float ci[4] = {s01.x, s01.y, s23.x, s23.y};
                float fr = 0.5f * (float)(fi + 1);
                #pragma unroll
                for (int e = 0; e < 4; e++) {
                    float pw = cr[e] * cr[e] + ci[e] * ci[e];
                    num[e] = fmaf(pw, fr, num[e]);
                    den[e] += pw;
                }
            }
        }
        #pragma unroll
        for (int e = 0; e < 4; e++) { num[e] = wred(num[e]); den[e] = wred(den[e]); }

        float sb[4] = {0.f,0.f,0.f,0.f}, sv0[4] = {0.f,0.f,0.f,0.f}, sv1[4] = {0.f,0.f,0.f,0.f};
        #pragma unroll
        for (int j = 0; j < 4; j++) {
            int t = lane + 32 * j;
            if (t < 121) {
                float4 l4 = *(const float4*)(lt + t * 8 + ebase);
                float le[4] = {l4.x, l4.y, l4.z, l4.w};
                #pragma unroll
                for (int e = 0; e < 4; e++) {
                    int eg = ebase + e;
                    sb[e] += le[e];
                    sv0[e] = fmaf(le[e], fcw[(eg * 2 + 0) * 121 + t], sv0[e]);
                    sv1[e] = fmaf(le[e], fcw[(eg * 2 + 1) * 121 + t], sv1[e]);
                }
            }
        }
        float bo_[4], v0[4], v1[4];
        #pragma unroll
        for (int e = 0; e < 4; e++) {
            int eg = ebase + e;
            bo_[e] = wred(sb[e]) * (1.f / 121.f);
            v0[e] = wred(sv0[e]) + fcb[eg * 2];
            v1[e] = wred(sv1[e]) + fcb[eg * 2 + 1];
        }

        float fe[4], am[4], ph[4];
        #pragma unroll
        for (int e = 0; e < 4; e++) {
            fe[e] = num[e] / den[e];
            am[e] = 2.f * sqrtf(den[e]) * (1.f / 121.f);
            ph[e] = atan2f(v1[e], v0[e]);
        }

        if (n == 0) {
            if (lane == 0) {
                #pragma unroll
                for (int e = 0; e < 4; e++) {
                    int eg = ebase + e;
                    out[OFF_P  + b * 8 + eg] = ph[e] * (1.f / TPIF);
                    out[OFF_FQ + b * 8 + eg] = fe[e];
                    out[OFF_A  + b * 8 + eg] = am[e];
                    out[OFF_B  + b * 8 + eg] = bo_[e];
                }
            }
            #pragma unroll
            for (int e = 0; e < 4; e++) {
                int eg = ebase + e;
                for (int t = lane; t < 121; t += 32)
                    out[OFF_LAT + (b * 8 + eg) * 121 + t] = lt[t * 8 + eg];
            }
        }

        #pragma unroll
        for (int e = 0; e < 4; e++) {
            int eg = ebase + e;
            float* yd = g_ys + ((size_t)(b * 8 + eg) * 240 + n) * 121;
            float w = TPIF * fe[e];
            for (int t = lane; t < 121; t += 32) {
                float arg = fmaf(w, (float)(t - 60) * (1.f / 60.f), ph[e]);
                yd[t] = fmaf(am[e], sinf(arg), bo_[e]);
            }
        }
    }
}

// ---------------- overlap-add (deterministic gather) ----------------
__global__ void overlap_k(float* __restrict__ out) {
    int be = blockIdx.x;
    int j = threadIdx.x; // 0..359
    const float* ys = g_ys + (size_t)be * 240 * 121;
    int tlo = j - 239; if (tlo < 0) tlo = 0;
    int thi = j < 120 ? j : 120;
    float s = 0.f;
    for (int t = tlo; t <= thi; t++) s += ys[(j - t) * 121 + t];
    float w = (j < 121) ? (float)(j + 1) : (j > 239 ? (float)(360 - j) : 121.f);
    float sig = s / w;
    if (j < 121) out[OFF_SIG + be * 121 + j] = sig;
    g_scy[be * 360 + j] = (j >= 60 && j < 300) ? sig : 0.f;
}

// ---------------- decoder conv1 (bias skipped: cancels in BN) ----------------
__global__ void __launch_bounds__(256) dec1_k(const float* __restrict__ dw1) {
    __shared__ float ys[8 * 360], ws[8 * 121];
    int b = blockIdx.x, o = blockIdx.y, tid = threadIdx.x;
    for (int i = tid; i < 8 * 360; i += 256)
        ys[i] = g_scy[(b * 8 + i / 360) * 360 + i % 360];
    for (int i = tid; i < 8 * 121; i += 256)
        ws[i] = dw1[o * 8 * 121 + i];
    __syncthreads();
    if (tid < 240) {
        float acc = 0.f;
        #pragma unroll
        for (int e = 0; e < 8; e++) {
            const float* yr = ys + e * 360 + tid;
            const float* wr = ws + e * 121;
            #pragma unroll 4
            for (int k = 0; k < 121; k++) acc = fmaf(wr[k], yr[k], acc);
        }
        g_dpre[(b * 24 + o) * 240 + tid] = acc;
    }
}

// ---------------- BN stats (deterministic tree) ----------------
__global__ void bnstat_k() {
    __shared__ float r1[256], r2[256];
    int o = blockIdx.x, tid = threadIdx.x;
    float s1 = 0.f, s2 = 0.f;
    for (int i = tid; i < 3840; i += 256) {
        int bb = i / 240, t = i - 240 * bb;
        float v = g_dpre[(bb * 24 + o) * 240 + t];
        s1 += v; s2 += v * v;
    }
    r1[tid] = s1; r2[tid] = s2; __syncthreads();
    for (int st = 128; st > 0; st >>= 1) {
        if (tid < st) { r1[tid] += r1[tid + st]; r2[tid] += r2[tid + st]; }
        __syncthreads();
    }
    if (tid == 0) {
        float m = r1[0] * (1.f / 3840.f);
        g_bnm[o] = m;
        g_bni[o] = rsqrtf(r2[0] * (1.f / 3840.f) - m * m + 1e-5f);
    }
}

__global__ void bnapply_k(const float* __restrict__ gam, const float* __restrict__ bet) {
    int idx = blockIdx.x * blockDim.x + threadIdx.x;
    if (idx >= 16 * 24 * 360) return;
    int tau = idx % 360, bo = idx / 360;
    int o = bo % 24;
    float v = 0.f;
    if (tau >= 60 && tau < 300)
        v = tanhf((g_dpre[bo * 240 + tau - 60] - g_bnm[o]) * g_bni[o] * gam[o] + bet[o]);
    g_ddp[idx] = v;
}

// ---------------- decoder conv2 + outputs ----------------
__global__ void __launch_bounds__(64) dec2_k(const float* __restrict__ dw2,
                                             const float* __restrict__ db2,
                                             float* __restrict__ out) {
    __shared__ float dd[24 * 360], ws[24 * 121];
    int b = blockIdx.x, c = blockIdx.y, tid = threadIdx.x;
    for (int i = tid; i < 24 * 360; i += 64) dd[i] = g_ddp[b * 24 * 360 + i];
    for (int i = tid; i < 24 * 121; i += 64) ws[i] = dw2[c * 24 * 121 + i];
    __syncthreads();
    if (tid < 60) {
        int t0 = tid * 4;
        float a0 = 0.f, a1 = 0.f, a2 = 0.f, a3 = 0.f;
        for (int o = 0; o < 24; o++) {
            const float* dr = dd + o * 360 + t0;
            const float* wr = ws + o * 121;
            float x0 = dr[0], x1 = dr[1], x2 = dr[2];
            #pragma unroll 4
            for (int k = 0; k < 121; k++) {
                float w = wr[k]; float x3 = dr[k + 3];
                a0 = fmaf(w, x0, a0); a1 = fmaf(w, x1, a1);
                a2 = fmaf(w, x2, a2); a3 = fmaf(w, x3, a3);
                x0 = x1; x1 = x2; x2 = x3;
            }
        }
        float bias = db2[c];
        float r[4] = { a0 + bias, a1 + bias, a2 + bias, a3 + bias };
        size_t yb = (size_t)(b * 72 + c) * 240 + t0;
        #pragma unroll
        for (int q = 0; q < 4; q++) {
            out[OFF_Y + yb + q] = r[q];
            int t = t0 + q;
            if (t < 121) out[OFF_YP + (b * 72 + c) * 121 + t] = r[q];
        }
    }
}

// ---------------- launch ----------------
extern "C" void kernel_launch(void* const* d_in, const int* in_sizes, int n_in,
                              void* d_out, int out_size) {
    const float* x   = (const float*)d_in[0];
    const float* w1  = (const float*)d_in[1];
    const float* lna = (const float*)d_in[3];
    const float* lnb = (const float*)d_in[4];
    const float* w2  = (const float*)d_in[5];
    const float* b2  = (const float*)d_in[6];
    const float* fcw = (const float*)d_in[7];
    const float* fcb = (const float*)d_in[8];
    const float* dw1 = (const float*)d_in[9];
    const float* bng = (const float*)d_in[11];
    const float* bnb = (const float*)d_in[12];
    const float* dw2 = (const float*)d_in[13];
    const float* db2 = (const float*)d_in[14];
    float* out = (float*)d_out;

    const int SMEM_S = (72 * 244 + 24 * 72) * 4;      // 77184
    const int SMEM_E = 4 * 3200 * 4;                  // 51200
    cudaFuncSetAttribute(s_kernel, cudaFuncAttributeMaxDynamicSharedMemorySize, SMEM_S);
    cudaFuncSetAttribute(encode_k, cudaFuncAttributeMaxDynamicSharedMemorySize, SMEM_E);

    prep_k<<<64, 256>>>(w2);
    s_kernel<<<dim3(121, 16), 256, SMEM_S>>>(x, w1);
    prefix_k<<<384, 256>>>();
    encode_k<<<960, 128, SMEM_E>>>(lna, lnb, b2, fcw, fcb, out);
    overlap_k<<<128, 360>>>(out);
    dec1_k<<<dim3(16, 24), 256>>>(dw1);
    bnstat_k<<<24, 256>>>();
    bnapply_k<<<540, 256>>>(bng, bnb);
    dec2_k<<<dim3(16, 72), 64>>>(dw2, db2, out);
}

// round 15
// speedup vs baseline: 1.2863x; 1.2268x over previous
#include <cuda_runtime.h>
#include <cuda_bf16.h>
#include <math.h>

// ---------------- constants ----------------
#define TPIF 6.283185307179586f
#define OFF_Y    0
#define OFF_LAT  276480
#define OFF_SIG  291968
#define OFF_P    307456
#define OFF_FQ   307584
#define OFF_A    307712
#define OFF_B    307840
#define OFF_YP   307968

// ---------------- scratch ----------------
__device__ float  g_P[(size_t)16*24*121*240];   // S then k-prefix: [b][o][k][Q]
__device__ float4 g_twid4[121*64];              // (cs,cs,sn,sn) [t][f] for DFT-121 params
__device__ float2 g_W[24*129*8];                // 0.5*FFT256(wrev) spectrum: [(o*129+f)*8+e]
__device__ float2 g_fftw[256];                  // FFT twiddles tw[half+m] = exp(-i pi m/half)
__device__ int    g_brev[256];                  // 8-bit reversal
__device__ float  g_ys[(size_t)16*8*240*121];   // ysin [b][e][n][t]
__device__ float  g_scy[16*8*360];              // padded yc
__device__ float  g_dpre[16*24*240];            // dec conv1 pre-BN
__device__ float  g_bnm[24];
__device__ float  g_bni[24];
__device__ float  g_ddp[16*24*360];             // tanh(BN(d)) padded

#define FULLMASK 0xffffffffu
__device__ __forceinline__ float wred(float v) {
    v += __shfl_xor_sync(FULLMASK, v, 16);
    v += __shfl_xor_sync(FULLMASK, v, 8);
    v += __shfl_xor_sync(FULLMASK, v, 4);
    v += __shfl_xor_sync(FULLMASK, v, 2);
    v += __shfl_xor_sync(FULLMASK, v, 1);
    return v;
}

// packed f32x2 helpers (epilogue DFT-121)
__device__ __forceinline__ void ffma2(unsigned long long& d, unsigned long long a, unsigned long long b) {
    asm("fma.rn.f32x2 %0, %1, %2, %0;" : "+l"(d) : "l"(a), "l"(b));
}
__device__ __forceinline__ float2 unpack2(unsigned long long v) {
    unsigned lo, hi;
    asm("mov.b64 {%0, %1}, %2;" : "=r"(lo), "=r"(hi) : "l"(v));
    return make_float2(__uint_as_float(lo), __uint_as_float(hi));
}

// ---------------- prep: tables + W spectrum ----------------
__global__ void prep_k(const float* __restrict__ w2) {
    int i = blockIdx.x * blockDim.x + threadIdx.x;
    int stride = gridDim.x * blockDim.x;
    // DFT-121 twiddles for params
    for (int idx = i; idx < 121 * 61; idx += stride) {
        int t = idx / 61, f = idx - 61 * t;
        float fr = (float)fmod((double)(2 * f * t) / 121.0, 2.0);
        float sn, cs; sincospif(fr, &sn, &cs);
        g_twid4[t * 64 + f] = make_float4(cs, cs, sn, sn);
    }
    // FFT-256 twiddles: tw[half+m] = exp(-i*pi*m/half)
    for (int idx = i; idx < 256; idx += stride) {
        if (idx == 0) { g_fftw[0] = make_float2(1.f, 0.f); }
        else {
            int h2 = 1 << (31 - __clz(idx));
            int m = idx - h2;
            float sn, cs; sincospif(-(float)m / (float)h2, &sn, &cs);
            g_fftw[idx] = make_float2(cs, sn);
        }
        g_brev[idx] = (int)(__brev((unsigned)idx) >> 24);
    }
    // W spectrum: W[o][f][e] = 0.5 * sum_j w2[e,o,120-j] * exp(-2 pi i f j / 256)
    for (int idx = i; idx < 24 * 8 * 129; idx += stride) {
        int e = idx & 7;
        int of = idx >> 3;
        int o = of / 129, f = of - 129 * o;
        float wr = 0.f, wi = 0.f;
        const float* wrow = w2 + (e * 24 + o) * 121;
        for (int j = 0; j <= 120; j++) {
            float wv = wrow[120 - j];
            int r = (f * j) & 255;
            float sn, cs; sincospif(-(float)r * (1.f / 128.f), &sn, &cs);
            wr = fmaf(wv, cs, wr);
            wi = fmaf(wv, sn, wi);
        }
        g_W[(o * 129 + f) * 8 + e] = make_float2(0.5f * wr, 0.5f * wi);
    }
}

// ---------------- S[b,o,k,Q] ----------------
__global__ void __launch_bounds__(256) s_kernel(const float* __restrict__ x,
                                                const float* __restrict__ w1) {
    extern __shared__ float sm[];
    float* xs = sm;               // 72 x 244 (dup-padded)
    float* ws = sm + 72 * 244;    // 24 x 72
    const int k = blockIdx.x, b = blockIdx.y;
    const int tid = threadIdx.x;

    for (int idx = tid; idx < 72 * 240; idx += 256) {
        int i = idx / 240, c = idx - 240 * i;
        xs[i * 244 + c] = x[(b * 72 + i) * 240 + c];
    }
    for (int idx = tid; idx < 72 * 4; idx += 256) {
        int i = idx >> 2, j = idx & 3;
        xs[i * 244 + 240 + j] = x[(b * 72 + i) * 240 + j];
    }
    for (int idx = tid; idx < 24 * 72; idx += 256)
        ws[idx] = w1[idx * 121 + k];
    __syncthreads();

    for (int task = tid; task < 360; task += 256) {
        int og = task / 60, qg = task - 60 * og;
        int o0 = og * 4, Q0 = qg * 4;
        float acc[4][4];
        #pragma unroll
        for (int a = 0; a < 4; a++)
            #pragma unroll
            for (int q = 0; q < 4; q++) acc[a][q] = 0.f;
        int base = Q0 + k + 120; if (base >= 240) base -= 240;
        const float* xb = xs + base;
        const float* wp0 = ws + (o0 + 0) * 72;
        const float* wp1 = ws + (o0 + 1) * 72;
        const float* wp2 = ws + (o0 + 2) * 72;
        const float* wp3 = ws + (o0 + 3) * 72;
        #pragma unroll 4
        for (int i = 0; i < 72; i++) {
            const float* xr = xb + i * 244;
            float x0 = xr[0], x1 = xr[1], x2 = xr[2], x3 = xr[3];
            float w0 = wp0[i], w1v = wp1[i], w2v = wp2[i], w3v = wp3[i];
            acc[0][0]=fmaf(w0,x0,acc[0][0]); acc[0][1]=fmaf(w0,x1,acc[0][1]);
            acc[0][2]=fmaf(w0,x2,acc[0][2]); acc[0][3]=fmaf(w0,x3,acc[0][3]);
            acc[1][0]=fmaf(w1v,x0,acc[1][0]); acc[1][1]=fmaf(w1v,x1,acc[1][1]);
            acc[1][2]=fmaf(w1v,x2,acc[1][2]); acc[1][3]=fmaf(w1v,x3,acc[1][3]);
            acc[2][0]=fmaf(w2v,x0,acc[2][0]); acc[2][1]=fmaf(w2v,x1,acc[2][1]);
            acc[2][2]=fmaf(w2v,x2,acc[2][2]); acc[2][3]=fmaf(w2v,x3,acc[2][3]);
            acc[3][0]=fmaf(w3v,x0,acc[3][0]); acc[3][1]=fmaf(w3v,x1,acc[3][1]);
            acc[3][2]=fmaf(w3v,x2,acc[3][2]); acc[3][3]=fmaf(w3v,x3,acc[3][3]);
        }
        size_t pbase = ((size_t)(b * 24 + o0) * 121 + k) * 240 + Q0;
        #pragma unroll
        for (int oo = 0; oo < 4; oo++)
            #pragma unroll
            for (int qq = 0; qq < 4; qq++)
                g_P[pbase + (size_t)oo * 121 * 240 + qq] = acc[oo][qq];
    }
}

// ---------------- prefix over k ----------------
__global__ void prefix_k() {
    int bo = blockIdx.x, Q = threadIdx.x;
    if (Q < 240) {
        size_t base = (size_t)bo * 121 * 240 + Q;
        float acc = 0.f;
        for (int k = 0; k < 121; k++) {
            acc += g_P[base + (size_t)k * 240];
            g_P[base + (size_t)k * 240] = acc;
        }
    }
}

// ---------------- warp-collective FFT-256 (DIT, bit-reversed in, natural out) ----
__device__ __forceinline__ void fft256(float2* __restrict__ X,
                                       const float2* __restrict__ tw, int lane) {
    #pragma unroll
    for (int s = 0; s < 8; s++) {
        const int half = 1 << s;
        #pragma unroll
        for (int u = 0; u < 4; u++) {
            int bfy = lane + 32 * u;
            int m = bfy & (half - 1);
            int p = ((bfy >> s) << (s + 1)) | m;
            float2 w = tw[half + m];
            float2 a = X[p];
            float2 bv = X[p + half];
            float vr = bv.x * w.x - bv.y * w.y;
            float vi = bv.x * w.y + bv.y * w.x;
            X[p]        = make_float2(a.x + vr, a.y + vi);
            X[p + half] = make_float2(a.x - vr, a.y - vi);
        }
        __syncwarp();
    }
}

// ---------------- encoder v7: conv2 via FFT-256; warp = 1 window ----------------
// block = 128 thr = 4 warps = 4 windows.
// per-warp slot (3616 floats): X float2[256] @0, Acc float2[8*132] @512, lt[976] @2624
// tables at 4*3616: tw float2[256], brev int[256]
__global__ void __launch_bounds__(128, 3) encode_k(
    const float* __restrict__ lna, const float* __restrict__ lnb,
    const float* __restrict__ b2, const float* __restrict__ fcw,
    const float* __restrict__ fcb, float* __restrict__ out)
{
    extern __shared__ float sm[];
    const int warp = threadIdx.x >> 5, lane = threadIdx.x & 31;
    float* slot = sm + warp * 3616;
    float2* X    = (float2*)slot;            // 256 complex
    float2* Acc  = (float2*)(slot + 512);    // [e][132]
    float* lt    = slot + 2624;              // lt[t*8+e]
    float2* twS  = (float2*)(sm + 4 * 3616); // 256 complex
    int*    brv  = (int*)(sm + 4 * 3616 + 512);
    const int s  = blockIdx.x * 4 + warp;
    const int b  = s / 240, n = s - b * 240;

    // load tables (block-wide)
    for (int i = threadIdx.x; i < 256; i += 128) {
        twS[i] = g_fftw[i];
        brv[i] = g_brev[i];
    }
    __syncthreads();

    // zero Acc
    for (int i = lane; i < 8 * 132; i += 32) Acc[i] = make_float2(0.f, 0.f);
    __syncwarp();

    // hoisted LN params
    float lnav[4], lnbv[4];
    #pragma unroll
    for (int j = 0; j < 4; j++) {
        int t = lane + 32 * j;
        lnav[j] = (t < 121) ? lna[t] : 0.f;
        lnbv[j] = (t < 121) ? lnb[t] : 0.f;
    }

    const size_t pb0 = (size_t)(b * 24) * 121 * 240;

    // ---- per o-pair: conv1+LN+tanh -> packed FFT -> unpack -> accumulate ----
    for (int p = 0; p < 12; p++) {
        float hpair[2][4];
        #pragma unroll
        for (int half = 0; half < 2; half++) {
            int o = 2 * p + half;
            const float* P = g_P + pb0 + (size_t)o * 121 * 240;
            float hv[4]; float s1 = 0.f, s2 = 0.f;
            #pragma unroll
            for (int j = 0; j < 4; j++) {
                int t = lane + 32 * j;
                float h = 0.f;
                if (t < 121) {
                    int Q = n + t; if (Q >= 240) Q -= 240;
                    if (t < 60) h = P[120 * 240 + Q] - P[(59 - t) * 240 + Q];
                    else        h = P[(180 - t) * 240 + Q];
                    s1 += h; s2 += h * h;
                }
                hv[j] = h;
            }
            s1 = wred(s1); s2 = wred(s2);
            float mean = s1 * (1.f / 121.f);
            float var = (s2 - s1 * mean) * (1.f / 120.f);
            float inv = 1.f / (sqrtf(var) + 1e-5f);
            #pragma unroll
            for (int j = 0; j < 4; j++) {
                int t = lane + 32 * j;
                hpair[half][j] = (t < 121)
                    ? tanhf((hv[j] - mean) * inv * lnav[j] + lnbv[j]) : 0.f;
            }
        }
        // zero X, scatter packed input at bit-reversed positions
        #pragma unroll
        for (int u = 0; u < 8; u++) X[lane + 32 * u] = make_float2(0.f, 0.f);
        __syncwarp();
        #pragma unroll
        for (int j = 0; j < 4; j++) {
            int t = lane + 32 * j;
            if (t < 121) X[brv[t]] = make_float2(hpair[0][j], hpair[1][j]);
        }
        __syncwarp();

        fft256(X, twS, lane);

        // unpack Hermitian halves + accumulate spectrum (0.5 folded into g_W)
        const float2* W0 = g_W + (size_t)(2 * p) * 129 * 8;
        const float2* W1 = g_W + (size_t)(2 * p + 1) * 129 * 8;
        #pragma unroll
        for (int r = 0; r < 5; r++) {
            int f = lane + 32 * r;
            bool act = (r < 4) || (lane == 0);
            if (act) {
                float2 Za = X[f];
                float2 Zc = X[(256 - f) & 255];
                float har = Za.x + Zc.x, hai = Za.y - Zc.y;   // 2*Ha
                float hbr = Za.y + Zc.y, hbi = Zc.x - Za.x;   // 2*Hb
                const float2* w0f = W0 + f * 8;
                const float2* w1f = W1 + f * 8;
                #pragma unroll
                for (int e = 0; e < 8; e++) {
                    float2 wa = w0f[e], wb = w1f[e];
                    float2 ac = Acc[e * 132 + f];
                    ac.x += wa.x * har - wa.y * hai + wb.x * hbr - wb.y * hbi;
                    ac.y += wa.x * hai + wa.y * har + wb.x * hbi + wb.y * hbr;
                    Acc[e * 132 + f] = ac;
                }
            }
        }
        __syncwarp();
    }

    // ---- inverse: per e-pair, build conj-packed spectrum, FFT, extract ----
    #pragma unroll
    for (int ep = 0; ep < 4; ep++) {
        const int ea = 2 * ep, eb = 2 * ep + 1;
        #pragma unroll
        for (int u = 0; u < 8; u++) {
            int nn = lane + 32 * u;
            float2 C;
            if (nn <= 128) {
                float2 Aa = Acc[ea * 132 + nn];
                float2 Ab = Acc[eb * 132 + nn];
                C = make_float2(Aa.x - Ab.y, -(Aa.y + Ab.x));
            } else {
                int g = 256 - nn;
                float2 Aa = Acc[ea * 132 + g];
                float2 Ab = Acc[eb * 132 + g];
                C = make_float2(Aa.x + Ab.y, Aa.y - Ab.x);
            }
            X[brv[nn]] = C;
        }
        __syncwarp();

        fft256(X, twS, lane);

        float bea = b2[ea], beb = b2[eb];
        #pragma unroll
        for (int j = 0; j < 4; j++) {
            int t = lane + 32 * j;
            if (t < 121) {
                float2 oz = X[t + 60];
                lt[t * 8 + ea] =  oz.x * (1.f / 256.f) + bea;
                lt[t * 8 + eb] = -oz.y * (1.f / 256.f) + beb;
            }
        }
        __syncwarp();
    }

    // ---- epilogue: DFT-121 params (8 e's), fc, outputs, resynthesis ----
    float num[8], den[8];
    #pragma unroll
    for (int e = 0; e < 8; e++) { num[e] = 0.f; den[e] = 0.f; }
    #pragma unroll
    for (int round = 0; round < 2; round++) {
        int fi = lane + 32 * round;
        if (fi < 60) {
            unsigned long long cr[4] = {0,0,0,0}, ci[4] = {0,0,0,0};
            const ulonglong2* tw2 = (const ulonglong2*)g_twid4 + fi + 1;
            for (int t = 0; t < 121; t++) {
                ulonglong2 wv = tw2[t * 64];
                ulonglong2 l01 = *(const ulonglong2*)(lt + t * 8);
                ulonglong2 l23 = *(const ulonglong2*)(lt + t * 8 + 4);
                ffma2(cr[0], wv.x, l01.x); ffma2(cr[1], wv.x, l01.y);
                ffma2(cr[2], wv.x, l23.x); ffma2(cr[3], wv.x, l23.y);
                ffma2(ci[0], wv.y, l01.x); ffma2(ci[1], wv.y, l01.y);
                ffma2(ci[2], wv.y, l23.x); ffma2(ci[3], wv.y, l23.y);
            }
            float fr = 0.5f * (float)(fi + 1);
            #pragma unroll
            for (int q = 0; q < 4; q++) {
                float2 C = unpack2(cr[q]), S = unpack2(ci[q]);
                float pw0 = C.x * C.x + S.x * S.x;
                float pw1 = C.y * C.y + S.y * S.y;
                num[2*q]   = fmaf(pw0, fr, num[2*q]);   den[2*q]   += pw0;
                num[2*q+1] = fmaf(pw1, fr, num[2*q+1]); den[2*q+1] += pw1;
            }
        }
    }
    #pragma unroll
    for (int e = 0; e < 8; e++) { num[e] = wred(num[e]); den[e] = wred(den[e]); }

    float sb[8], sv0[8], sv1[8];
    #pragma unroll
    for (int e = 0; e < 8; e++) { sb[e] = 0.f; sv0[e] = 0.f; sv1[e] = 0.f; }
    #pragma unroll
    for (int j = 0; j < 4; j++) {
        int t = lane + 32 * j;
        if (t < 121) {
            #pragma unroll
            for (int e = 0; e < 8; e++) {
                float le = lt[t * 8 + e];
                sb[e] += le;
                sv0[e] = fmaf(le, fcw[(e * 2 + 0) * 121 + t], sv0[e]);
                sv1[e] = fmaf(le, fcw[(e * 2 + 1) * 121 + t], sv1[e]);
            }
        }
    }
    float fe[8], am[8], ph[8], bo_[8];
    #pragma unroll
    for (int e = 0; e < 8; e++) {
        bo_[e] = wred(sb[e]) * (1.f / 121.f);
        float v0 = wred(sv0[e]) + fcb[e * 2];
        float v1 = wred(sv1[e]) + fcb[e * 2 + 1];
        fe[e] = num[e] / den[e];
        am[e] = 2.f * sqrtf(den[e]) * (1.f / 121.f);
        ph[e] = atan2f(v1, v0);
    }

    if (n == 0) {
        if (lane == 0) {
            #pragma unroll
            for (int e = 0; e < 8; e++) {
                out[OFF_P  + b * 8 + e] = ph[e] * (1.f / TPIF);
                out[OFF_FQ + b * 8 + e] = fe[e];
                out[OFF_A  + b * 8 + e] = am[e];
                out[OFF_B  + b * 8 + e] = bo_[e];
            }
        }
        #pragma unroll
        for (int e = 0; e < 8; e++)
            for (int t = lane; t < 121; t += 32)
                out[OFF_LAT + (b * 8 + e) * 121 + t] = lt[t * 8 + e];
    }

    #pragma unroll
    for (int e = 0; e < 8; e++) {
        float* yd = g_ys + ((size_t)(b * 8 + e) * 240 + n) * 121;
        float wv = TPIF * fe[e];
        for (int t = lane; t < 121; t += 32) {
            float arg = fmaf(wv, (float)(t - 60) * (1.f / 60.f), ph[e]);
            yd[t] = fmaf(am[e], sinf(arg), bo_[e]);
        }
    }
}

// ---------------- overlap-add (deterministic gather) ----------------
__global__ void overlap_k(float* __restrict__ out) {
    int be = blockIdx.x;
    int j = threadIdx.x; // 0..359
    const float* ys = g_ys + (size_t)be * 240 * 121;
    int tlo = j - 239; if (tlo < 0) tlo = 0;
    int thi = j < 120 ? j : 120;
    float s = 0.f;
    for (int t = tlo; t <= thi; t++) s += ys[(j - t) * 121 + t];
    float w = (j < 121) ? (float)(j + 1) : (j > 239 ? (float)(360 - j) : 121.f);
    float sig = s / w;
    if (j < 121) out[OFF_SIG + be * 121 + j] = sig;
    g_scy[be * 360 + j] = (j >= 60 && j < 300) ? sig : 0.f;
}

// ---------------- decoder conv1 (bias skipped: cancels in BN) ----------------
__global__ void __launch_bounds__(256) dec1_k(const float* __restrict__ dw1) {
    __shared__ float ys[8 * 360], ws[8 * 121];
    int b = blockIdx.x, o = blockIdx.y, tid = threadIdx.x;
    for (int i = tid; i < 8 * 360; i += 256)
        ys[i] = g_scy[(b * 8 + i / 360) * 360 + i % 360];
    for (int i = tid; i < 8 * 121; i += 256)
        ws[i] = dw1[o * 8 * 121 + i];
    __syncthreads();
    if (tid < 240) {
        float acc = 0.f;
        #pragma unroll
        for (int e = 0; e < 8; e++) {
            const float* yr = ys + e * 360 + tid;
            const float* wr = ws + e * 121;
            #pragma unroll 4
            for (int k = 0; k < 121; k++) acc = fmaf(wr[k], yr[k], acc);
        }
        g_dpre[(b * 24 + o) * 240 + tid] = acc;
    }
}

// ---------------- BN stats (deterministic tree) ----------------
__global__ void bnstat_k() {
    __shared__ float r1[256], r2[256];
    int o = blockIdx.x, tid = threadIdx.x;
    float s1 = 0.f, s2 = 0.f;
    for (int i = tid; i < 3840; i += 256) {
        int bb = i / 240, t = i - 240 * bb;
        float v = g_dpre[(bb * 24 + o) * 240 + t];
        s1 += v; s2 += v * v;
    }
    r1[tid] = s1; r2[tid] = s2; __syncthreads();
    for (int st = 128; st > 0; st >>= 1) {
        if (tid < st) { r1[tid] += r1[tid + st]; r2[tid] += r2[tid + st]; }
        __syncthreads();
    }
    if (tid == 0) {
        float m = r1[0] * (1.f / 3840.f);
        g_bnm[o] = m;
        g_bni[o] = rsqrtf(r2[0] * (1.f / 3840.f) - m * m + 1e-5f);
    }
}

__global__ void bnapply_k(const float* __restrict__ gam, const float* __restrict__ bet) {
    int idx = blockIdx.x * blockDim.x + threadIdx.x;
    if (idx >= 16 * 24 * 360) return;
    int tau = idx % 360, bo = idx / 360;
    int o = bo % 24;
    float v = 0.f;
    if (tau >= 60 && tau < 300)
        v = tanhf((g_dpre[bo * 240 + tau - 60] - g_bnm[o]) * g_bni[o] * gam[o] + bet[o]);
    g_ddp[idx] = v;
}

// ---------------- decoder conv2 + outputs ----------------
__global__ void __launch_bounds__(64) dec2_k(const float* __restrict__ dw2,
                                             const float* __restrict__ db2,
                                             float* __restrict__ out) {
    __shared__ float dd[24 * 360], ws[24 * 121];
    int b = blockIdx.x, c = blockIdx.y, tid = threadIdx.x;
    for (int i = tid; i < 24 * 360; i += 64) dd[i] = g_ddp[b * 24 * 360 + i];
    for (int i = tid; i < 24 * 121; i += 64) ws[i] = dw2[c * 24 * 121 + i];
    __syncthreads();
    if (tid < 60) {
        int t0 = tid * 4;
        float a0 = 0.f, a1 = 0.f, a2 = 0.f, a3 = 0.f;
        for (int o = 0; o < 24; o++) {
            const float* dr = dd + o * 360 + t0;
            const float* wr = ws + o * 121;
            float x0 = dr[0], x1 = dr[1], x2 = dr[2];
            #pragma unroll 4
            for (int k = 0; k < 121; k++) {
                float w = wr[k]; float x3 = dr[k + 3];
                a0 = fmaf(w, x0, a0); a1 = fmaf(w, x1, a1);
                a2 = fmaf(w, x2, a2); a3 = fmaf(w, x3, a3);
                x0 = x1; x1 = x2; x2 = x3;
            }
        }
        float bias = db2[c];
        float r[4] = { a0 + bias, a1 + bias, a2 + bias, a3 + bias };
        size_t yb = (size_t)(b * 72 + c) * 240 + t0;
        #pragma unroll
        for (int q = 0; q < 4; q++) {
            out[OFF_Y + yb + q] = r[q];
            int t = t0 + q;
            if (t < 121) out[OFF_YP + (b * 72 + c) * 121 + t] = r[q];
        }
    }
}

// ---------------- launch ----------------
extern "C" void kernel_launch(void* const* d_in, const int* in_sizes, int n_in,
                              void* d_out, int out_size) {
    const float* x   = (const float*)d_in[0];
    const float* w1  = (const float*)d_in[1];
    const float* lna = (const float*)d_in[3];
    const float* lnb = (const float*)d_in[4];
    const float* w2  = (const float*)d_in[5];
    const float* b2  = (const float*)d_in[6];
    const float* fcw = (const float*)d_in[7];
    const float* fcb = (const float*)d_in[8];
    const float* dw1 = (const float*)d_in[9];
    const float* bng = (const float*)d_in[11];
    const float* bnb = (const float*)d_in[12];
    const float* dw2 = (const float*)d_in[13];
    const float* db2 = (const float*)d_in[14];
    float* out = (float*)d_out;

    const int SMEM_S = (72 * 244 + 24 * 72) * 4;            // 77184
    const int SMEM_E = (4 * 3616 + 512 + 256) * 4;          // 60928
    cudaFuncSetAttribute(s_kernel, cudaFuncAttributeMaxDynamicSharedMemorySize, SMEM_S);
    cudaFuncSetAttribute(encode_k, cudaFuncAttributeMaxDynamicSharedMemorySize, SMEM_E);

    prep_k<<<128, 256>>>(w2);
    s_kernel<<<dim3(121, 16), 256, SMEM_S>>>(x, w1);
    prefix_k<<<384, 256>>>();
    encode_k<<<960, 128, SMEM_E>>>(lna, lnb, b2, fcw, fcb, out);
    overlap_k<<<128, 360>>>(out);
    dec1_k<<<dim3(16, 24), 256>>>(dw1);
    bnstat_k<<<24, 256>>>();
    bnapply_k<<<540, 256>>>(bng, bnb);
    dec2_k<<<dim3(16, 72), 64>>>(dw2, db2, out);
}

// round 16
// speedup vs baseline: 1.3445x; 1.0452x over previous
#include <cuda_runtime.h>
#include <cuda_bf16.h>
#include <math.h>

// ---------------- constants ----------------
#define TPIF 6.283185307179586f
#define OFF_Y    0
#define OFF_LAT  276480
#define OFF_SIG  291968
#define OFF_P    307456
#define OFF_FQ   307584
#define OFF_A    307712
#define OFF_B    307840
#define OFF_YP   307968

// ---------------- scratch ----------------
__device__ float  g_P[(size_t)16*24*121*240];   // S then k-prefix: [b][o][k][Q]
__device__ float4 g_twid4[121*64];              // (cs,cs,sn,sn) [t][f] for DFT-121 params
__device__ float2 g_W[24*129*8];                // 0.5*FFT256(wrev) spectrum: [(o*129+f)*8+e]
__device__ float2 g_fftw[256];                  // FFT twiddles tw[half+m] = exp(-i pi m/half)
__device__ int    g_brev[256];                  // 8-bit reversal
__device__ float  g_ys[(size_t)16*8*240*121];   // ysin [b][e][n][t]
__device__ float  g_scy[16*8*360];              // padded yc
__device__ float  g_dpre[16*24*240];            // dec conv1 pre-BN
__device__ float  g_bnm[24];
__device__ float  g_bni[24];
__device__ float  g_ddp[16*24*360];             // tanh(BN(d)) padded

#define FULLMASK 0xffffffffu
__device__ __forceinline__ float wred(float v) {
    v += __shfl_xor_sync(FULLMASK, v, 16);
    v += __shfl_xor_sync(FULLMASK, v, 8);
    v += __shfl_xor_sync(FULLMASK, v, 4);
    v += __shfl_xor_sync(FULLMASK, v, 2);
    v += __shfl_xor_sync(FULLMASK, v, 1);
    return v;
}

// packed f32x2 helpers (epilogue DFT-121)
__device__ __forceinline__ void ffma2(unsigned long long& d, unsigned long long a, unsigned long long b) {
    asm("fma.rn.f32x2 %0, %1, %2, %0;" : "+l"(d) : "l"(a), "l"(b));
}
__device__ __forceinline__ float2 unpack2(unsigned long long v) {
    unsigned lo, hi;
    asm("mov.b64 {%0, %1}, %2;" : "=r"(lo), "=r"(hi) : "l"(v));
    return make_float2(__uint_as_float(lo), __uint_as_float(hi));
}

__device__ __forceinline__ float2 cmulf(float2 a, float2 b) {
    return make_float2(a.x * b.x - a.y * b.y, a.x * b.y + a.y * b.x);
}

// ---------------- prep: tables + W spectrum ----------------
__global__ void prep_k(const float* __restrict__ w2) {
    int i = blockIdx.x * blockDim.x + threadIdx.x;
    int stride = gridDim.x * blockDim.x;
    for (int idx = i; idx < 121 * 61; idx += stride) {
        int t = idx / 61, f = idx - 61 * t;
        float fr = (float)fmod((double)(2 * f * t) / 121.0, 2.0);
        float sn, cs; sincospif(fr, &sn, &cs);
        g_twid4[t * 64 + f] = make_float4(cs, cs, sn, sn);
    }
    for (int idx = i; idx < 256; idx += stride) {
        if (idx == 0) { g_fftw[0] = make_float2(1.f, 0.f); }
        else {
            int h2 = 1 << (31 - __clz(idx));
            int m = idx - h2;
            float sn, cs; sincospif(-(float)m / (float)h2, &sn, &cs);
            g_fftw[idx] = make_float2(cs, sn);
        }
        g_brev[idx] = (int)(__brev((unsigned)idx) >> 24);
    }
    for (int idx = i; idx < 24 * 8 * 129; idx += stride) {
        int e = idx & 7;
        int of = idx >> 3;
        int o = of / 129, f = of - 129 * o;
        float wr = 0.f, wi = 0.f;
        const float* wrow = w2 + (e * 24 + o) * 121;
        for (int j = 0; j <= 120; j++) {
            float wv = wrow[120 - j];
            int r = (f * j) & 255;
            float sn, cs; sincospif(-(float)r * (1.f / 128.f), &sn, &cs);
            wr = fmaf(wv, cs, wr);
            wi = fmaf(wv, sn, wi);
        }
        g_W[(o * 129 + f) * 8 + e] = make_float2(0.5f * wr, 0.5f * wi);
    }
}

// ---------------- S[b,o,k,Q] ----------------
__global__ void __launch_bounds__(256) s_kernel(const float* __restrict__ x,
                                                const float* __restrict__ w1) {
    extern __shared__ float sm[];
    float* xs = sm;               // 72 x 244 (dup-padded)
    float* ws = sm + 72 * 244;    // 24 x 72
    const int k = blockIdx.x, b = blockIdx.y;
    const int tid = threadIdx.x;

    for (int idx = tid; idx < 72 * 240; idx += 256) {
        int i = idx / 240, c = idx - 240 * i;
        xs[i * 244 + c] = x[(b * 72 + i) * 240 + c];
    }
    for (int idx = tid; idx < 72 * 4; idx += 256) {
        int i = idx >> 2, j = idx & 3;
        xs[i * 244 + 240 + j] = x[(b * 72 + i) * 240 + j];
    }
    for (int idx = tid; idx < 24 * 72; idx += 256)
        ws[idx] = w1[idx * 121 + k];
    __syncthreads();

    for (int task = tid; task < 360; task += 256) {
        int og = task / 60, qg = task - 60 * og;
        int o0 = og * 4, Q0 = qg * 4;
        float acc[4][4];
        #pragma unroll
        for (int a = 0; a < 4; a++)
            #pragma unroll
            for (int q = 0; q < 4; q++) acc[a][q] = 0.f;
        int base = Q0 + k + 120; if (base >= 240) base -= 240;
        const float* xb = xs + base;
        const float* wp0 = ws + (o0 + 0) * 72;
        const float* wp1 = ws + (o0 + 1) * 72;
        const float* wp2 = ws + (o0 + 2) * 72;
        const float* wp3 = ws + (o0 + 3) * 72;
        #pragma unroll 4
        for (int i = 0; i < 72; i++) {
            const float* xr = xb + i * 244;
            float x0 = xr[0], x1 = xr[1], x2 = xr[2], x3 = xr[3];
            float w0 = wp0[i], w1v = wp1[i], w2v = wp2[i], w3v = wp3[i];
            acc[0][0]=fmaf(w0,x0,acc[0][0]); acc[0][1]=fmaf(w0,x1,acc[0][1]);
            acc[0][2]=fmaf(w0,x2,acc[0][2]); acc[0][3]=fmaf(w0,x3,acc[0][3]);
            acc[1][0]=fmaf(w1v,x0,acc[1][0]); acc[1][1]=fmaf(w1v,x1,acc[1][1]);
            acc[1][2]=fmaf(w1v,x2,acc[1][2]); acc[1][3]=fmaf(w1v,x3,acc[1][3]);
            acc[2][0]=fmaf(w2v,x0,acc[2][0]); acc[2][1]=fmaf(w2v,x1,acc[2][1]);
            acc[2][2]=fmaf(w2v,x2,acc[2][2]); acc[2][3]=fmaf(w2v,x3,acc[2][3]);
            acc[3][0]=fmaf(w3v,x0,acc[3][0]); acc[3][1]=fmaf(w3v,x1,acc[3][1]);
            acc[3][2]=fmaf(w3v,x2,acc[3][2]); acc[3][3]=fmaf(w3v,x3,acc[3][3]);
        }
        size_t pbase = ((size_t)(b * 24 + o0) * 121 + k) * 240 + Q0;
        #pragma unroll
        for (int oo = 0; oo < 4; oo++)
            #pragma unroll
            for (int qq = 0; qq < 4; qq++)
                g_P[pbase + (size_t)oo * 121 * 240 + qq] = acc[oo][qq];
    }
}

// ---------------- prefix over k ----------------
__global__ void prefix_k() {
    int bo = blockIdx.x, Q = threadIdx.x;
    if (Q < 240) {
        size_t base = (size_t)bo * 121 * 240 + Q;
        float acc = 0.f;
        for (int k = 0; k < 121; k++) {
            acc += g_P[base + (size_t)k * 240];
            g_P[base + (size_t)k * 240] = acc;
        }
    }
}

// ---------------- register/shuffle FFT-256 ----------------
// v[u] = X[32u+lane] in the DIT j-domain (bit-reversed input, natural output).
// Stages 0..4 exchange across lanes (shfl); stages 5..7 are register-local.
struct FftTw {
    float2 w1, s2, s3, s4, t5, t6a, t6b, t70, t71, t72, t73;
};

__device__ __forceinline__ void bfly_shfl(float2& v, float2 w, int bit, int lane) {
    float2 o;
    o.x = __shfl_xor_sync(FULLMASK, v.x, bit);
    o.y = __shfl_xor_sync(FULLMASK, v.y, bit);
    float sgn = (lane & bit) ? -1.f : 1.f;
    float2 base = (lane & bit) ? o : v;
    float2 oper = (lane & bit) ? v : o;
    float2 t = cmulf(w, oper);
    v.x = fmaf(sgn, t.x, base.x);
    v.y = fmaf(sgn, t.y, base.y);
}

#define BFR(a, b, w) { \
    float2 _t = cmulf(w, v[b]); \
    v[b] = make_float2(v[a].x - _t.x, v[a].y - _t.y); \
    v[a] = make_float2(v[a].x + _t.x, v[a].y + _t.y); }

__device__ __forceinline__ void fft256_reg(float2* v, const FftTw& ft, int lane) {
    // stage 0 (w = 1)
    #pragma unroll
    for (int u = 0; u < 8; u++) {
        float2 o;
        o.x = __shfl_xor_sync(FULLMASK, v[u].x, 1);
        o.y = __shfl_xor_sync(FULLMASK, v[u].y, 1);
        float sgn = (lane & 1) ? -1.f : 1.f;
        float2 base = (lane & 1) ? o : v[u];
        float2 oper = (lane & 1) ? v[u] : o;
        v[u].x = fmaf(sgn, oper.x, base.x);
        v[u].y = fmaf(sgn, oper.y, base.y);
    }
    // stages 1..4
    #pragma unroll
    for (int u = 0; u < 8; u++) bfly_shfl(v[u], ft.w1, 2, lane);
    #pragma unroll
    for (int u = 0; u < 8; u++) bfly_shfl(v[u], ft.s2, 4, lane);
    #pragma unroll
    for (int u = 0; u < 8; u++) bfly_shfl(v[u], ft.s3, 8, lane);
    #pragma unroll
    for (int u = 0; u < 8; u++) bfly_shfl(v[u], ft.s4, 16, lane);
    // stage 5: pairs (0,1)(2,3)(4,5)(6,7), w = t5
    BFR(0,1,ft.t5) BFR(2,3,ft.t5) BFR(4,5,ft.t5) BFR(6,7,ft.t5)
    // stage 6: pairs (0,2)(1,3)(4,6)(5,7)
    BFR(0,2,ft.t6a) BFR(1,3,ft.t6b) BFR(4,6,ft.t6a) BFR(5,7,ft.t6b)
    // stage 7: pairs (0,4)(1,5)(2,6)(3,7)
    BFR(0,4,ft.t70) BFR(1,5,ft.t71) BFR(2,6,ft.t72) BFR(3,7,ft.t73)
}

// run FFT on X in smem via registers
__device__ __forceinline__ void fft256(float2* __restrict__ X,
                                       const FftTw& ft, int lane) {
    float2 v[8];
    #pragma unroll
    for (int u = 0; u < 8; u++) v[u] = X[u * 32 + lane];
    fft256_reg(v, ft, lane);
    #pragma unroll
    for (int u = 0; u < 8; u++) X[u * 32 + lane] = v[u];
    __syncwarp();
}

// ---------------- encoder v8: conv2 via register-FFT-256; warp = 1 window ------
__global__ void __launch_bounds__(128, 3) encode_k(
    const float* __restrict__ lna, const float* __restrict__ lnb,
    const float* __restrict__ b2, const float* __restrict__ fcw,
    const float* __restrict__ fcb, float* __restrict__ out)
{
    extern __shared__ float sm[];
    const int warp = threadIdx.x >> 5, lane = threadIdx.x & 31;
    float* slot = sm + warp * 3616;
    float2* X    = (float2*)slot;            // 256 complex
    float2* Acc  = (float2*)(slot + 512);    // [e][132]
    float* lt    = slot + 2624;              // lt[t*8+e]
    float2* twS  = (float2*)(sm + 4 * 3616); // 256 complex
    int*    brv  = (int*)(sm + 4 * 3616 + 512);
    const int s  = blockIdx.x * 4 + warp;
    const int b  = s / 240, n = s - b * 240;

    for (int i = threadIdx.x; i < 256; i += 128) {
        twS[i] = g_fftw[i];
        brv[i] = g_brev[i];
    }
    __syncthreads();

    // preload per-lane FFT twiddles into registers
    FftTw ft;
    ft.w1  = (lane & 1) ? make_float2(0.f, -1.f) : make_float2(1.f, 0.f);
    ft.s2  = twS[4  + (lane & 3)];
    ft.s3  = twS[8  + (lane & 7)];
    ft.s4  = twS[16 + (lane & 15)];
    ft.t5  = twS[32  + lane];
    ft.t6a = twS[64  + lane];
    ft.t6b = twS[96  + lane];
    ft.t70 = twS[128 + lane];
    ft.t71 = twS[160 + lane];
    ft.t72 = twS[192 + lane];
    ft.t73 = twS[224 + lane];

    // zero Acc
    for (int i = lane; i < 8 * 132; i += 32) Acc[i] = make_float2(0.f, 0.f);
    __syncwarp();

    // hoisted LN params
    float lnav[4], lnbv[4];
    #pragma unroll
    for (int j = 0; j < 4; j++) {
        int t = lane + 32 * j;
        lnav[j] = (t < 121) ? lna[t] : 0.f;
        lnbv[j] = (t < 121) ? lnb[t] : 0.f;
    }

    const size_t pb0 = (size_t)(b * 24) * 121 * 240;

    // ---- per o-pair: conv1+LN+tanh -> packed FFT -> unpack -> accumulate ----
    for (int p = 0; p < 12; p++) {
        float hpair[2][4];
        #pragma unroll
        for (int half = 0; half < 2; half++) {
            int o = 2 * p + half;
            const float* P = g_P + pb0 + (size_t)o * 121 * 240;
            float hv[4]; float s1 = 0.f, s2 = 0.f;
            #pragma unroll
            for (int j = 0; j < 4; j++) {
                int t = lane + 32 * j;
                float h = 0.f;
                if (t < 121) {
                    int Q = n + t; if (Q >= 240) Q -= 240;
                    if (t < 60) h = P[120 * 240 + Q] - P[(59 - t) * 240 + Q];
                    else        h = P[(180 - t) * 240 + Q];
                    s1 += h; s2 += h * h;
                }
                hv[j] = h;
            }
            s1 = wred(s1); s2 = wred(s2);
            float mean = s1 * (1.f / 121.f);
            float var = (s2 - s1 * mean) * (1.f / 120.f);
            float inv = 1.f / (sqrtf(var) + 1e-5f);
            #pragma unroll
            for (int j = 0; j < 4; j++) {
                int t = lane + 32 * j;
                hpair[half][j] = (t < 121)
                    ? tanhf((hv[j] - mean) * inv * lnav[j] + lnbv[j]) : 0.f;
            }
        }
        // zero X, scatter packed input at bit-reversed positions
        #pragma unroll
        for (int u = 0; u < 8; u++) X[lane + 32 * u] = make_float2(0.f, 0.f);
        __syncwarp();
        #pragma unroll
        for (int j = 0; j < 4; j++) {
            int t = lane + 32 * j;
            if (t < 121) X[brv[t]] = make_float2(hpair[0][j], hpair[1][j]);
        }
        __syncwarp();

        fft256(X, ft, lane);

        // unpack Hermitian halves + accumulate spectrum (0.5 folded into g_W)
        const float2* W0 = g_W + (size_t)(2 * p) * 129 * 8;
        const float2* W1 = g_W + (size_t)(2 * p + 1) * 129 * 8;
        #pragma unroll
        for (int r = 0; r < 5; r++) {
            int f = lane + 32 * r;
            bool act = (r < 4) || (lane == 0);
            if (act) {
                float2 Za = X[f];
                float2 Zc = X[(256 - f) & 255];
                float har = Za.x + Zc.x, hai = Za.y - Zc.y;   // 2*Ha
                float hbr = Za.y + Zc.y, hbi = Zc.x - Za.x;   // 2*Hb
                const float2* w0f = W0 + f * 8;
                const float2* w1f = W1 + f * 8;
                #pragma unroll
                for (int e = 0; e < 8; e++) {
                    float2 wa = w0f[e], wb = w1f[e];
                    float2 ac = Acc[e * 132 + f];
                    ac.x += wa.x * har - wa.y * hai + wb.x * hbr - wb.y * hbi;
                    ac.y += wa.x * hai + wa.y * har + wb.x * hbi + wb.y * hbr;
                    Acc[e * 132 + f] = ac;
                }
            }
        }
        __syncwarp();
    }

    // ---- inverse: per e-pair, build conj-packed spectrum, FFT, extract ----
    #pragma unroll
    for (int ep = 0; ep < 4; ep++) {
        const int ea = 2 * ep, eb = 2 * ep + 1;
        #pragma unroll
        for (int u = 0; u < 8; u++) {
            int nn = lane + 32 * u;
            float2 C;
            if (nn <= 128) {
                float2 Aa = Acc[ea * 132 + nn];
                float2 Ab = Acc[eb * 132 + nn];
                C = make_float2(Aa.x - Ab.y, -(Aa.y + Ab.x));
            } else {
                int g = 256 - nn;
                float2 Aa = Acc[ea * 132 + g];
                float2 Ab = Acc[eb * 132 + g];
                C = make_float2(Aa.x + Ab.y, Aa.y - Ab.x);
            }
            X[brv[nn]] = C;
        }
        __syncwarp();

        fft256(X, ft, lane);

        float bea = b2[ea], beb = b2[eb];
        #pragma unroll
        for (int j = 0; j < 4; j++) {
            int t = lane + 32 * j;
            if (t < 121) {
                float2 oz = X[t + 60];
                lt[t * 8 + ea] =  oz.x * (1.f / 256.f) + bea;
                lt[t * 8 + eb] = -oz.y * (1.f / 256.f) + beb;
            }
        }
        __syncwarp();
    }

    // ---- epilogue: DFT-121 params (8 e's), fc, outputs, resynthesis ----
    float num[8], den[8];
    #pragma unroll
    for (int e = 0; e < 8; e++) { num[e] = 0.f; den[e] = 0.f; }
    #pragma unroll
    for (int round = 0; round < 2; round++) {
        int fi = lane + 32 * round;
        if (fi < 60) {
            unsigned long long cr[4] = {0,0,0,0}, ci[4] = {0,0,0,0};
            const ulonglong2* tw2 = (const ulonglong2*)g_twid4 + fi + 1;
            for (int t = 0; t < 121; t++) {
                ulonglong2 wv = tw2[t * 64];
                ulonglong2 l01 = *(const ulonglong2*)(lt + t * 8);
                ulonglong2 l23 = *(const ulonglong2*)(lt + t * 8 + 4);
                ffma2(cr[0], wv.x, l01.x); ffma2(cr[1], wv.x, l01.y);
                ffma2(cr[2], wv.x, l23.x); ffma2(cr[3], wv.x, l23.y);
                ffma2(ci[0], wv.y, l01.x); ffma2(ci[1], wv.y, l01.y);
                ffma2(ci[2], wv.y, l23.x); ffma2(ci[3], wv.y, l23.y);
            }
            float fr = 0.5f * (float)(fi + 1);
            #pragma unroll
            for (int q = 0; q < 4; q++) {
                float2 C = unpack2(cr[q]), S = unpack2(ci[q]);
                float pw0 = C.x * C.x + S.x * S.x;
                float pw1 = C.y * C.y + S.y * S.y;
                num[2*q]   = fmaf(pw0, fr, num[2*q]);   den[2*q]   += pw0;
                num[2*q+1] = fmaf(pw1, fr, num[2*q+1]); den[2*q+1] += pw1;
            }
        }
    }
    #pragma unroll
    for (int e = 0; e < 8; e++) { num[e] = wred(num[e]); den[e] = wred(den[e]); }

    float sb[8], sv0[8], sv1[8];
    #pragma unroll
    for (int e = 0; e < 8; e++) { sb[e] = 0.f; sv0[e] = 0.f; sv1[e] = 0.f; }
    #pragma unroll
    for (int j = 0; j < 4; j++) {
        int t = lane + 32 * j;
        if (t < 121) {
            #pragma unroll
            for (int e = 0; e < 8; e++) {
                float le = lt[t * 8 + e];
                sb[e] += le;
                sv0[e] = fmaf(le, fcw[(e * 2 + 0) * 121 + t], sv0[e]);
                sv1[e] = fmaf(le, fcw[(e * 2 + 1) * 121 + t], sv1[e]);
            }
        }
    }
    float fe[8], am[8], ph[8], bo_[8];
    #pragma unroll
    for (int e = 0; e < 8; e++) {
        bo_[e] = wred(sb[e]) * (1.f / 121.f);
        float v0 = wred(sv0[e]) + fcb[e * 2];
        float v1 = wred(sv1[e]) + fcb[e * 2 + 1];
        fe[e] = num[e] / den[e];
        am[e] = 2.f * sqrtf(den[e]) * (1.f / 121.f);
        ph[e] = atan2f(v1, v0);
    }

    if (n == 0) {
        if (lane == 0) {
            #pragma unroll
            for (int e = 0; e < 8; e++) {
                out[OFF_P  + b * 8 + e] = ph[e] * (1.f / TPIF);
                out[OFF_FQ + b * 8 + e] = fe[e];
                out[OFF_A  + b * 8 + e] = am[e];
                out[OFF_B  + b * 8 + e] = bo_[e];
            }
        }
        #pragma unroll
        for (int e = 0; e < 8; e++)
            for (int t = lane; t < 121; t += 32)
                out[OFF_LAT + (b * 8 + e) * 121 + t] = lt[t * 8 + e];
    }

    #pragma unroll
    for (int e = 0; e < 8; e++) {
        float* yd = g_ys + ((size_t)(b * 8 + e) * 240 + n) * 121;
        float wv = TPIF * fe[e];
        for (int t = lane; t < 121; t += 32) {
            float arg = fmaf(wv, (float)(t - 60) * (1.f / 60.f), ph[e]);
            yd[t] = fmaf(am[e], sinf(arg), bo_[e]);
        }
    }
}

// ---------------- overlap-add (deterministic gather) ----------------
__global__ void overlap_k(float* __restrict__ out) {
    int be = blockIdx.x;
    int j = threadIdx.x; // 0..359
    const float* ys = g_ys + (size_t)be * 240 * 121;
    int tlo = j - 239; if (tlo < 0) tlo = 0;
    int thi = j < 120 ? j : 120;
    float s = 0.f;
    for (int t = tlo; t <= thi; t++) s += ys[(j - t) * 121 + t];
    float w = (j < 121) ? (float)(j + 1) : (j > 239 ? (float)(360 - j) : 121.f);
    float sig = s / w;
    if (j < 121) out[OFF_SIG + be * 121 + j] = sig;
    g_scy[be * 360 + j] = (j >= 60 && j < 300) ? sig : 0.f;
}

// ---------------- decoder conv1 (bias skipped: cancels in BN) ----------------
__global__ void __launch_bounds__(256) dec1_k(const float* __restrict__ dw1) {
    __shared__ float ys[8 * 360], ws[8 * 121];
    int b = blockIdx.x, o = blockIdx.y, tid = threadIdx.x;
    for (int i = tid; i < 8 * 360; i += 256)
        ys[i] = g_scy[(b * 8 + i / 360) * 360 + i % 360];
    for (int i = tid; i < 8 * 121; i += 256)
        ws[i] = dw1[o * 8 * 121 + i];
    __syncthreads();
    if (tid < 240) {
        float acc = 0.f;
        #pragma unroll
        for (int e = 0; e < 8; e++) {
            const float* yr = ys + e * 360 + tid;
            const float* wr = ws + e * 121;
            #pragma unroll 4
            for (int k = 0; k < 121; k++) acc = fmaf(wr[k], yr[k], acc);
        }
        g_dpre[(b * 24 + o) * 240 + tid] = acc;
    }
}

// ---------------- BN stats (deterministic tree) ----------------
__global__ void bnstat_k() {
    __shared__ float r1[256], r2[256];
    int o = blockIdx.x, tid = threadIdx.x;
    float s1 = 0.f, s2 = 0.f;
    for (int i = tid; i < 3840; i += 256) {
        int bb = i / 240, t = i - 240 * bb;
        float v = g_dpre[(bb * 24 + o) * 240 + t];
        s1 += v; s2 += v * v;
    }
    r1[tid] = s1; r2[tid] = s2; __syncthreads();
    for (int st = 128; st > 0; st >>= 1) {
        if (tid < st) { r1[tid] += r1[tid + st]; r2[tid] += r2[tid + st]; }
        __syncthreads();
    }
    if (tid == 0) {
        float m = r1[0] * (1.f / 3840.f);
        g_bnm[o] = m;
        g_bni[o] = rsqrtf(r2[0] * (1.f / 3840.f) - m * m + 1e-5f);
    }
}

__global__ void bnapply_k(const float* __restrict__ gam, const float* __restrict__ bet) {
    int idx = blockIdx.x * blockDim.x + threadIdx.x;
    if (idx >= 16 * 24 * 360) return;
    int tau = idx % 360, bo = idx / 360;
    int o = bo % 24;
    float v = 0.f;
    if (tau >= 60 && tau < 300)
        v = tanhf((g_dpre[bo * 240 + tau - 60] - g_bnm[o]) * g_bni[o] * gam[o] + bet[o]);
    g_ddp[idx] = v;
}

// ---------------- decoder conv2 + outputs ----------------
__global__ void __launch_bounds__(64) dec2_k(const float* __restrict__ dw2,
                                             const float* __restrict__ db2,
                                             float* __restrict__ out) {
    __shared__ float dd[24 * 360], ws[24 * 121];
    int b = blockIdx.x, c = blockIdx.y, tid = threadIdx.x;
    for (int i = tid; i < 24 * 360; i += 64) dd[i] = g_ddp[b * 24 * 360 + i];
    for (int i = tid; i < 24 * 121; i += 64) ws[i] = dw2[c * 24 * 121 + i];
    __syncthreads();
    if (tid < 60) {
        int t0 = tid * 4;
        float a0 = 0.f, a1 = 0.f, a2 = 0.f, a3 = 0.f;
        for (int o = 0; o < 24; o++) {
            const float* dr = dd + o * 360 + t0;
            const float* wr = ws + o * 121;
            float x0 = dr[0], x1 = dr[1], x2 = dr[2];
            #pragma unroll 4
            for (int k = 0; k < 121; k++) {
                float w = wr[k]; float x3 = dr[k + 3];
                a0 = fmaf(w, x0, a0); a1 = fmaf(w, x1, a1);
                a2 = fmaf(w, x2, a2); a3 = fmaf(w, x3, a3);
                x0 = x1; x1 = x2; x2 = x3;
            }
        }
        float bias = db2[c];
        float r[4] = { a0 + bias, a1 + bias, a2 + bias, a3 + bias };
        size_t yb = (size_t)(b * 72 + c) * 240 + t0;
        #pragma unroll
        for (int q = 0; q < 4; q++) {
            out[OFF_Y + yb + q] = r[q];
            int t = t0 + q;
            if (t < 121) out[OFF_YP + (b * 72 + c) * 121 + t] = r[q];
        }
    }
}

// ---------------- launch ----------------
extern "C" void kernel_launch(void* const* d_in, const int* in_sizes, int n_in,
                              void* d_out, int out_size) {
    const float* x   = (const float*)d_in[0];
    const float* w1  = (const float*)d_in[1];
    const float* lna = (const float*)d_in[3];
    const float* lnb = (const float*)d_in[4];
    const float* w2  = (const float*)d_in[5];
    const float* b2  = (const float*)d_in[6];
    const float* fcw = (const float*)d_in[7];
    const float* fcb = (const float*)d_in[8];
    const float* dw1 = (const float*)d_in[9];
    const float* bng = (const float*)d_in[11];
    const float* bnb = (const float*)d_in[12];
    const float* dw2 = (const float*)d_in[13];
    const float* db2 = (const float*)d_in[14];
    float* out = (float*)d_out;

    const int SMEM_S = (72 * 244 + 24 * 72) * 4;            // 77184
    const int SMEM_E = (4 * 3616 + 512 + 256) * 4;          // 60928
    cudaFuncSetAttribute(s_kernel, cudaFuncAttributeMaxDynamicSharedMemorySize, SMEM_S);
    cudaFuncSetAttribute(encode_k, cudaFuncAttributeMaxDynamicSharedMemorySize, SMEM_E);

    prep_k<<<128, 256>>>(w2);
    s_kernel<<<dim3(121, 16), 256, SMEM_S>>>(x, w1);
    prefix_k<<<384, 256>>>();
    encode_k<<<960, 128, SMEM_E>>>(lna, lnb, b2, fcw, fcb, out);
    overlap_k<<<128, 360>>>(out);
    dec1_k<<<dim3(16, 24), 256>>>(dw1);
    bnstat_k<<<24, 256>>>();
    bnapply_k<<<540, 256>>>(bng, bnb);
    dec2_k<<<dim3(16, 72), 64>>>(dw2, db2, out);
}

// round 17
// speedup vs baseline: 1.3816x; 1.0276x over previous
#include <cuda_runtime.h>
#include <cuda_bf16.h>
#include <math.h>

// ---------------- constants ----------------
#define TPIF 6.283185307179586f
#define OFF_Y    0
#define OFF_LAT  276480
#define OFF_SIG  291968
#define OFF_P    307456
#define OFF_FQ   307584
#define OFF_A    307712
#define OFF_B    307840
#define OFF_YP   307968

// Acc layout: f-major, ACCS floats per f (8 complex used, padded for banks)
#define ACCS 20

// ---------------- scratch ----------------
__device__ float  g_P[(size_t)16*24*121*240];   // S then k-prefix: [b][o][k][Q]
__device__ float4 g_twid4[121*64];              // (cs,cs,sn,sn) [t][f] for DFT-121 params
__device__ float2 g_W[24*129*8];                // 0.5*FFT256(wrev) spectrum: [(o*129+f)*8+e]
__device__ float2 g_fftw[256];                  // FFT twiddles tw[half+m] = exp(-i pi m/half)
__device__ int    g_brev[256];                  // 8-bit reversal
__device__ float  g_ys[(size_t)16*8*240*121];   // ysin [b][e][n][t]
__device__ float  g_scy[16*8*360];              // padded yc
__device__ float  g_dpre[16*24*240];            // dec conv1 pre-BN
__device__ float  g_bnm[24];
__device__ float  g_bni[24];
__device__ float  g_ddp[16*24*360];             // tanh(BN(d)) padded

#define FULLMASK 0xffffffffu
__device__ __forceinline__ float wred(float v) {
    v += __shfl_xor_sync(FULLMASK, v, 16);
    v += __shfl_xor_sync(FULLMASK, v, 8);
    v += __shfl_xor_sync(FULLMASK, v, 4);
    v += __shfl_xor_sync(FULLMASK, v, 2);
    v += __shfl_xor_sync(FULLMASK, v, 1);
    return v;
}

// packed f32x2 helpers (epilogue DFT-121)
__device__ __forceinline__ void ffma2(unsigned long long& d, unsigned long long a, unsigned long long b) {
    asm("fma.rn.f32x2 %0, %1, %2, %0;" : "+l"(d) : "l"(a), "l"(b));
}
__device__ __forceinline__ float2 unpack2(unsigned long long v) {
    unsigned lo, hi;
    asm("mov.b64 {%0, %1}, %2;" : "=r"(lo), "=r"(hi) : "l"(v));
    return make_float2(__uint_as_float(lo), __uint_as_float(hi));
}

__device__ __forceinline__ float2 cmulf(float2 a, float2 b) {
    return make_float2(a.x * b.x - a.y * b.y, a.x * b.y + a.y * b.x);
}

// ---------------- prep: tables + W spectrum ----------------
__global__ void prep_k(const float* __restrict__ w2) {
    int i = blockIdx.x * blockDim.x + threadIdx.x;
    int stride = gridDim.x * blockDim.x;
    for (int idx = i; idx < 121 * 61; idx += stride) {
        int t = idx / 61, f = idx - 61 * t;
        float fr = (float)fmod((double)(2 * f * t) / 121.0, 2.0);
        float sn, cs; sincospif(fr, &sn, &cs);
        g_twid4[t * 64 + f] = make_float4(cs, cs, sn, sn);
    }
    for (int idx = i; idx < 256; idx += stride) {
        if (idx == 0) { g_fftw[0] = make_float2(1.f, 0.f); }
        else {
            int h2 = 1 << (31 - __clz(idx));
            int m = idx - h2;
            float sn, cs; sincospif(-(float)m / (float)h2, &sn, &cs);
            g_fftw[idx] = make_float2(cs, sn);
        }
        g_brev[idx] = (int)(__brev((unsigned)idx) >> 24);
    }
    for (int idx = i; idx < 24 * 8 * 129; idx += stride) {
        int e = idx & 7;
        int of = idx >> 3;
        int o = of / 129, f = of - 129 * o;
        float wr = 0.f, wi = 0.f;
        const float* wrow = w2 + (e * 24 + o) * 121;
        for (int j = 0; j <= 120; j++) {
            float wv = wrow[120 - j];
            int r = (f * j) & 255;
            float sn, cs; sincospif(-(float)r * (1.f / 128.f), &sn, &cs);
            wr = fmaf(wv, cs, wr);
            wi = fmaf(wv, sn, wi);
        }
        g_W[(o * 129 + f) * 8 + e] = make_float2(0.5f * wr, 0.5f * wi);
    }
}

// ---------------- S[b,o,k,Q] ----------------
__global__ void __launch_bounds__(256) s_kernel(const float* __restrict__ x,
                                                const float* __restrict__ w1) {
    extern __shared__ float sm[];
    float* xs = sm;               // 72 x 244 (dup-padded)
    float* ws = sm + 72 * 244;    // 24 x 72
    const int k = blockIdx.x, b = blockIdx.y;
    const int tid = threadIdx.x;

    for (int idx = tid; idx < 72 * 240; idx += 256) {
        int i = idx / 240, c = idx - 240 * i;
        xs[i * 244 + c] = x[(b * 72 + i) * 240 + c];
    }
    for (int idx = tid; idx < 72 * 4; idx += 256) {
        int i = idx >> 2, j = idx & 3;
        xs[i * 244 + 240 + j] = x[(b * 72 + i) * 240 + j];
    }
    for (int idx = tid; idx < 24 * 72; idx += 256)
        ws[idx] = w1[idx * 121 + k];
    __syncthreads();

    for (int task = tid; task < 360; task += 256) {
        int og = task / 60, qg = task - 60 * og;
        int o0 = og * 4, Q0 = qg * 4;
        float acc[4][4];
        #pragma unroll
        for (int a = 0; a < 4; a++)
            #pragma unroll
            for (int q = 0; q < 4; q++) acc[a][q] = 0.f;
        int base = Q0 + k + 120; if (base >= 240) base -= 240;
        const float* xb = xs + base;
        const float* wp0 = ws + (o0 + 0) * 72;
        const float* wp1 = ws + (o0 + 1) * 72;
        const float* wp2 = ws + (o0 + 2) * 72;
        const float* wp3 = ws + (o0 + 3) * 72;
        #pragma unroll 4
        for (int i = 0; i < 72; i++) {
            const float* xr = xb + i * 244;
            float x0 = xr[0], x1 = xr[1], x2 = xr[2], x3 = xr[3];
            float w0 = wp0[i], w1v = wp1[i], w2v = wp2[i], w3v = wp3[i];
            acc[0][0]=fmaf(w0,x0,acc[0][0]); acc[0][1]=fmaf(w0,x1,acc[0][1]);
            acc[0][2]=fmaf(w0,x2,acc[0][2]); acc[0][3]=fmaf(w0,x3,acc[0][3]);
            acc[1][0]=fmaf(w1v,x0,acc[1][0]); acc[1][1]=fmaf(w1v,x1,acc[1][1]);
            acc[1][2]=fmaf(w1v,x2,acc[1][2]); acc[1][3]=fmaf(w1v,x3,acc[1][3]);
            acc[2][0]=fmaf(w2v,x0,acc[2][0]); acc[2][1]=fmaf(w2v,x1,acc[2][1]);
            acc[2][2]=fmaf(w2v,x2,acc[2][2]); acc[2][3]=fmaf(w2v,x3,acc[2][3]);
            acc[3][0]=fmaf(w3v,x0,acc[3][0]); acc[3][1]=fmaf(w3v,x1,acc[3][1]);
            acc[3][2]=fmaf(w3v,x2,acc[3][2]); acc[3][3]=fmaf(w3v,x3,acc[3][3]);
        }
        size_t pbase = ((size_t)(b * 24 + o0) * 121 + k) * 240 + Q0;
        #pragma unroll
        for (int oo = 0; oo < 4; oo++)
            #pragma unroll
            for (int qq = 0; qq < 4; qq++)
                g_P[pbase + (size_t)oo * 121 * 240 + qq] = acc[oo][qq];
    }
}

// ---------------- prefix over k ----------------
__global__ void prefix_k() {
    int bo = blockIdx.x, Q = threadIdx.x;
    if (Q < 240) {
        size_t base = (size_t)bo * 121 * 240 + Q;
        float acc = 0.f;
        for (int k = 0; k < 121; k++) {
            acc += g_P[base + (size_t)k * 240];
            g_P[base + (size_t)k * 240] = acc;
        }
    }
}

// ---------------- register/shuffle FFT-256 ----------------
struct FftTw {
    float2 w1, s2, s3, s4, t5, t6a, t6b, t70, t71, t72, t73;
};

__device__ __forceinline__ void bfly_shfl(float2& v, float2 w, int bit, int lane) {
    float2 o;
    o.x = __shfl_xor_sync(FULLMASK, v.x, bit);
    o.y = __shfl_xor_sync(FULLMASK, v.y, bit);
    float sgn = (lane & bit) ? -1.f : 1.f;
    float2 base = (lane & bit) ? o : v;
    float2 oper = (lane & bit) ? v : o;
    float2 t = cmulf(w, oper);
    v.x = fmaf(sgn, t.x, base.x);
    v.y = fmaf(sgn, t.y, base.y);
}

#define BFR(a, b, w) { \
    float2 _t = cmulf(w, v[b]); \
    v[b] = make_float2(v[a].x - _t.x, v[a].y - _t.y); \
    v[a] = make_float2(v[a].x + _t.x, v[a].y + _t.y); }

__device__ __forceinline__ void fft256_reg(float2* v, const FftTw& ft, int lane) {
    #pragma unroll
    for (int u = 0; u < 8; u++) {
        float2 o;
        o.x = __shfl_xor_sync(FULLMASK, v[u].x, 1);
        o.y = __shfl_xor_sync(FULLMASK, v[u].y, 1);
        float sgn = (lane & 1) ? -1.f : 1.f;
        float2 base = (lane & 1) ? o : v[u];
        float2 oper = (lane & 1) ? v[u] : o;
        v[u].x = fmaf(sgn, oper.x, base.x);
        v[u].y = fmaf(sgn, oper.y, base.y);
    }
    #pragma unroll
    for (int u = 0; u < 8; u++) bfly_shfl(v[u], ft.w1, 2, lane);
    #pragma unroll
    for (int u = 0; u < 8; u++) bfly_shfl(v[u], ft.s2, 4, lane);
    #pragma unroll
    for (int u = 0; u < 8; u++) bfly_shfl(v[u], ft.s3, 8, lane);
    #pragma unroll
    for (int u = 0; u < 8; u++) bfly_shfl(v[u], ft.s4, 16, lane);
    BFR(0,1,ft.t5) BFR(2,3,ft.t5) BFR(4,5,ft.t5) BFR(6,7,ft.t5)
    BFR(0,2,ft.t6a) BFR(1,3,ft.t6b) BFR(4,6,ft.t6a) BFR(5,7,ft.t6b)
    BFR(0,4,ft.t70) BFR(1,5,ft.t71) BFR(2,6,ft.t72) BFR(3,7,ft.t73)
}

__device__ __forceinline__ void fft256(float2* __restrict__ X,
                                       const FftTw& ft, int lane) {
    float2 v[8];
    #pragma unroll
    for (int u = 0; u < 8; u++) v[u] = X[u * 32 + lane];
    fft256_reg(v, ft, lane);
    #pragma unroll
    for (int u = 0; u < 8; u++) X[u * 32 + lane] = v[u];
    __syncwarp();
}

// ---------------- encoder v9: register-FFT + vectorized f-major Acc ----------
// per-warp slot (4080 floats): X float2[256] @0, Acc [129][ACCS] @512, lt[976] @3092
__global__ void __launch_bounds__(128, 3) encode_k(
    const float* __restrict__ lna, const float* __restrict__ lnb,
    const float* __restrict__ b2, const float* __restrict__ fcw,
    const float* __restrict__ fcb, float* __restrict__ out)
{
    extern __shared__ float sm[];
    const int warp = threadIdx.x >> 5, lane = threadIdx.x & 31;
    float* slot = sm + warp * 4080;
    float2* X    = (float2*)slot;            // 256 complex
    float* Acc   = slot + 512;               // [129][ACCS]
    float* lt    = slot + 3092;              // lt[t*8+e]
    float2* twS  = (float2*)(sm + 4 * 4080); // 256 complex
    int*    brv  = (int*)(sm + 4 * 4080 + 512);
    const int s  = blockIdx.x * 4 + warp;
    const int b  = s / 240, n = s - b * 240;

    for (int i = threadIdx.x; i < 256; i += 128) {
        twS[i] = g_fftw[i];
        brv[i] = g_brev[i];
    }
    __syncthreads();

    // preload per-lane FFT twiddles into registers
    FftTw ft;
    ft.w1  = (lane & 1) ? make_float2(0.f, -1.f) : make_float2(1.f, 0.f);
    ft.s2  = twS[4  + (lane & 3)];
    ft.s3  = twS[8  + (lane & 7)];
    ft.s4  = twS[16 + (lane & 15)];
    ft.t5  = twS[32  + lane];
    ft.t6a = twS[64  + lane];
    ft.t6b = twS[96  + lane];
    ft.t70 = twS[128 + lane];
    ft.t71 = twS[160 + lane];
    ft.t72 = twS[192 + lane];
    ft.t73 = twS[224 + lane];

    // zero Acc
    for (int i = lane; i < 129 * ACCS; i += 32) Acc[i] = 0.f;
    __syncwarp();

    // hoisted LN params
    float lnav[4], lnbv[4];
    #pragma unroll
    for (int j = 0; j < 4; j++) {
        int t = lane + 32 * j;
        lnav[j] = (t < 121) ? lna[t] : 0.f;
        lnbv[j] = (t < 121) ? lnb[t] : 0.f;
    }

    const size_t pb0 = (size_t)(b * 24) * 121 * 240;

    // ---- per o-pair: conv1+LN+tanh -> packed FFT -> unpack -> accumulate ----
    for (int p = 0; p < 12; p++) {
        float hpair[2][4];
        #pragma unroll
        for (int half = 0; half < 2; half++) {
            int o = 2 * p + half;
            const float* P = g_P + pb0 + (size_t)o * 121 * 240;
            float hv[4]; float s1 = 0.f, s2 = 0.f;
            #pragma unroll
            for (int j = 0; j < 4; j++) {
                int t = lane + 32 * j;
                float h = 0.f;
                if (t < 121) {
                    int Q = n + t; if (Q >= 240) Q -= 240;
                    if (t < 60) h = P[120 * 240 + Q] - P[(59 - t) * 240 + Q];
                    else        h = P[(180 - t) * 240 + Q];
                    s1 += h; s2 += h * h;
                }
                hv[j] = h;
            }
            s1 = wred(s1); s2 = wred(s2);
            float mean = s1 * (1.f / 121.f);
            float var = (s2 - s1 * mean) * (1.f / 120.f);
            float inv = 1.f / (sqrtf(var) + 1e-5f);
            #pragma unroll
            for (int j = 0; j < 4; j++) {
                int t = lane + 32 * j;
                hpair[half][j] = (t < 121)
                    ? tanhf((hv[j] - mean) * inv * lnav[j] + lnbv[j]) : 0.f;
            }
        }
        // zero X, scatter packed input at bit-reversed positions
        #pragma unroll
        for (int u = 0; u < 8; u++) X[lane + 32 * u] = make_float2(0.f, 0.f);
        __syncwarp();
        #pragma unroll
        for (int j = 0; j < 4; j++) {
            int t = lane + 32 * j;
            if (t < 121) X[brv[t]] = make_float2(hpair[0][j], hpair[1][j]);
        }
        __syncwarp();

        fft256(X, ft, lane);

        // unpack Hermitian halves + accumulate spectrum (0.5 folded into g_W)
        const float2* W0 = g_W + (size_t)(2 * p) * 129 * 8;
        const float2* W1 = g_W + (size_t)(2 * p + 1) * 129 * 8;
        #pragma unroll
        for (int r = 0; r < 5; r++) {
            int f = lane + 32 * r;
            bool act = (r < 4) || (lane == 0);
            if (act) {
                float2 Za = X[f];
                float2 Zc = X[(256 - f) & 255];
                float har = Za.x + Zc.x, hai = Za.y - Zc.y;   // 2*Ha
                float hbr = Za.y + Zc.y, hbi = Zc.x - Za.x;   // 2*Hb
                const float4* w0q = (const float4*)(W0 + f * 8);
                const float4* w1q = (const float4*)(W1 + f * 8);
                float4* accq = (float4*)(Acc + f * ACCS);
                #pragma unroll
                for (int q = 0; q < 4; q++) {
                    float4 wa = w0q[q], wb = w1q[q];
                    float4 ac = accq[q];
                    ac.x += wa.x * har - wa.y * hai + wb.x * hbr - wb.y * hbi;
                    ac.y += wa.x * hai + wa.y * har + wb.x * hbi + wb.y * hbr;
                    ac.z += wa.z * har - wa.w * hai + wb.z * hbr - wb.w * hbi;
                    ac.w += wa.z * hai + wa.w * har + wb.z * hbi + wb.w * hbr;
                    accq[q] = ac;
                }
            }
        }
        __syncwarp();
    }

    // ---- inverse: per e-pair, build conj-packed spectrum, FFT, extract ----
    #pragma unroll
    for (int ep = 0; ep < 4; ep++) {
        const int ea = 2 * ep, eb = 2 * ep + 1;
        #pragma unroll
        for (int u = 0; u < 8; u++) {
            int nn = lane + 32 * u;
            float2 C;
            if (nn <= 128) {
                float4 qv = *(const float4*)(Acc + nn * ACCS + 4 * ep);
                C = make_float2(qv.x - qv.w, -(qv.y + qv.z));
            } else {
                int g = 256 - nn;
                float4 qv = *(const float4*)(Acc + g * ACCS + 4 * ep);
                C = make_float2(qv.x + qv.w, qv.y - qv.z);
            }
            X[brv[nn]] = C;
        }
        __syncwarp();

        fft256(X, ft, lane);

        float bea = b2[ea], beb = b2[eb];
        #pragma unroll
        for (int j = 0; j < 4; j++) {
            int t = lane + 32 * j;
            if (t < 121) {
                float2 oz = X[t + 60];
                lt[t * 8 + ea] =  oz.x * (1.f / 256.f) + bea;
                lt[t * 8 + eb] = -oz.y * (1.f / 256.f) + beb;
            }
        }
        __syncwarp();
    }

    // ---- epilogue: DFT-121 params (8 e's), fc, outputs, resynthesis ----
    float num[8], den[8];
    #pragma unroll
    for (int e = 0; e < 8; e++) { num[e] = 0.f; den[e] = 0.f; }
    #pragma unroll
    for (int round = 0; round < 2; round++) {
        int fi = lane + 32 * round;
        if (fi < 60) {
            unsigned long long cr[4] = {0,0,0,0}, ci[4] = {0,0,0,0};
            const ulonglong2* tw2 = (const ulonglong2*)g_twid4 + fi + 1;
            for (int t = 0; t < 121; t++) {
                ulonglong2 wv = tw2[t * 64];
                ulonglong2 l01 = *(const ulonglong2*)(lt + t * 8);
                ulonglong2 l23 = *(const ulonglong2*)(lt + t * 8 + 4);
                ffma2(cr[0], wv.x, l01.x); ffma2(cr[1], wv.x, l01.y);
                ffma2(cr[2], wv.x, l23.x); ffma2(cr[3], wv.x, l23.y);
                ffma2(ci[0], wv.y, l01.x); ffma2(ci[1], wv.y, l01.y);
                ffma2(ci[2], wv.y, l23.x); ffma2(ci[3], wv.y, l23.y);
            }
            float fr = 0.5f * (float)(fi + 1);
            #pragma unroll
            for (int q = 0; q < 4; q++) {
                float2 C = unpack2(cr[q]), S = unpack2(ci[q]);
                float pw0 = C.x * C.x + S.x * S.x;
                float pw1 = C.y * C.y + S.y * S.y;
                num[2*q]   = fmaf(pw0, fr, num[2*q]);   den[2*q]   += pw0;
                num[2*q+1] = fmaf(pw1, fr, num[2*q+1]); den[2*q+1] += pw1;
            }
        }
    }
    #pragma unroll
    for (int e = 0; e < 8; e++) { num[e] = wred(num[e]); den[e] = wred(den[e]); }

    float sb[8], sv0[8], sv1[8];
    #pragma unroll
    for (int e = 0; e < 8; e++) { sb[e] = 0.f; sv0[e] = 0.f; sv1[e] = 0.f; }
    #pragma unroll
    for (int j = 0; j < 4; j++) {
        int t = lane + 32 * j;
        if (t < 121) {
            #pragma unroll
            for (int e = 0; e < 8; e++) {
                float le = lt[t * 8 + e];
                sb[e] += le;
                sv0[e] = fmaf(le, fcw[(e * 2 + 0) * 121 + t], sv0[e]);
                sv1[e] = fmaf(le, fcw[(e * 2 + 1) * 121 + t], sv1[e]);
            }
        }
    }
    float fe[8], am[8], ph[8], bo_[8];
    #pragma unroll
    for (int e = 0; e < 8; e++) {
        bo_[e] = wred(sb[e]) * (1.f / 121.f);
        float v0 = wred(sv0[e]) + fcb[e * 2];
        float v1 = wred(sv1[e]) + fcb[e * 2 + 1];
        fe[e] = num[e] / den[e];
        am[e] = 2.f * sqrtf(den[e]) * (1.f / 121.f);
        ph[e] = atan2f(v1, v0);
    }

    if (n == 0) {
        if (lane == 0) {
            #pragma unroll
            for (int e = 0; e < 8; e++) {
                out[OFF_P  + b * 8 + e] = ph[e] * (1.f / TPIF);
                out[OFF_FQ + b * 8 + e] = fe[e];
                out[OFF_A  + b * 8 + e] = am[e];
                out[OFF_B  + b * 8 + e] = bo_[e];
            }
        }
        #pragma unroll
        for (int e = 0; e < 8; e++)
            for (int t = lane; t < 121; t += 32)
                out[OFF_LAT + (b * 8 + e) * 121 + t] = lt[t * 8 + e];
    }

    #pragma unroll
    for (int e = 0; e < 8; e++) {
        float* yd = g_ys + ((size_t)(b * 8 + e) * 240 + n) * 121;
        float wv = TPIF * fe[e];
        for (int t = lane; t < 121; t += 32) {
            float arg = fmaf(wv, (float)(t - 60) * (1.f / 60.f), ph[e]);
            yd[t] = fmaf(am[e], sinf(arg), bo_[e]);
        }
    }
}

// ---------------- overlap-add (deterministic gather) ----------------
__global__ void overlap_k(float* __restrict__ out) {
    int be = blockIdx.x;
    int j = threadIdx.x; // 0..359
    const float* ys = g_ys + (size_t)be * 240 * 121;
    int tlo = j - 239; if (tlo < 0) tlo = 0;
    int thi = j < 120 ? j : 120;
    float s = 0.f;
    for (int t = tlo; t <= thi; t++) s += ys[(j - t) * 121 + t];
    float w = (j < 121) ? (float)(j + 1) : (j > 239 ? (float)(360 - j) : 121.f);
    float sig = s / w;
    if (j < 121) out[OFF_SIG + be * 121 + j] = sig;
    g_scy[be * 360 + j] = (j >= 60 && j < 300) ? sig : 0.f;
}

// ---------------- decoder conv1 (bias skipped: cancels in BN) ----------------
__global__ void __launch_bounds__(256) dec1_k(const float* __restrict__ dw1) {
    __shared__ float ys[8 * 360], ws[8 * 121];
    int b = blockIdx.x, o = blockIdx.y, tid = threadIdx.x;
    for (int i = tid; i < 8 * 360; i += 256)
        ys[i] = g_scy[(b * 8 + i / 360) * 360 + i % 360];
    for (int i = tid; i < 8 * 121; i += 256)
        ws[i] = dw1[o * 8 * 121 + i];
    __syncthreads();
    if (tid < 240) {
        float acc = 0.f;
        #pragma unroll
        for (int e = 0; e < 8; e++) {
            const float* yr = ys + e * 360 + tid;
            const float* wr = ws + e * 121;
            #pragma unroll 4
            for (int k = 0; k < 121; k++) acc = fmaf(wr[k], yr[k], acc);
        }
        g_dpre[(b * 24 + o) * 240 + tid] = acc;
    }
}

// ---------------- BN stats (deterministic tree) ----------------
__global__ void bnstat_k() {
    __shared__ float r1[256], r2[256];
    int o = blockIdx.x, tid = threadIdx.x;
    float s1 = 0.f, s2 = 0.f;
    for (int i = tid; i < 3840; i += 256) {
        int bb = i / 240, t = i - 240 * bb;
        float v = g_dpre[(bb * 24 + o) * 240 + t];
        s1 += v; s2 += v * v;
    }
    r1[tid] = s1; r2[tid] = s2; __syncthreads();
    for (int st = 128; st > 0; st >>= 1) {
        if (tid < st) { r1[tid] += r1[tid + st]; r2[tid] += r2[tid + st]; }
        __syncthreads();
    }
    if (tid == 0) {
        float m = r1[0] * (1.f / 3840.f);
        g_bnm[o] = m;
        g_bni[o] = rsqrtf(r2[0] * (1.f / 3840.f) - m * m + 1e-5f);
    }
}

__global__ void bnapply_k(const float* __restrict__ gam, const float* __restrict__ bet) {
    int idx = blockIdx.x * blockDim.x + threadIdx.x;
    if (idx >= 16 * 24 * 360) return;
    int tau = idx % 360, bo = idx / 360;
    int o = bo % 24;
    float v = 0.f;
    if (tau >= 60 && tau < 300)
        v = tanhf((g_dpre[bo * 240 + tau - 60] - g_bnm[o]) * g_bni[o] * gam[o] + bet[o]);
    g_ddp[idx] = v;
}

// ---------------- decoder conv2 + outputs (240 active threads) --------------
__global__ void __launch_bounds__(256) dec2_k(const float* __restrict__ dw2,
                                              const float* __restrict__ db2,
                                              float* __restrict__ out) {
    __shared__ float dd[24 * 360], ws[24 * 121];
    int b = blockIdx.x, c = blockIdx.y, tid = threadIdx.x;
    for (int i = tid; i < 24 * 360; i += 256) dd[i] = g_ddp[b * 24 * 360 + i];
    for (int i = tid; i < 24 * 121; i += 256) ws[i] = dw2[c * 24 * 121 + i];
    __syncthreads();
    if (tid < 240) {
        float acc = 0.f;
        for (int o = 0; o < 24; o++) {
            const float* dr = dd + o * 360 + tid;
            const float* wr = ws + o * 121;
            #pragma unroll 4
            for (int k = 0; k < 121; k++) acc = fmaf(wr[k], dr[k], acc);
        }
        float r = acc + db2[c];
        out[OFF_Y + (size_t)(b * 72 + c) * 240 + tid] = r;
        if (tid < 121) out[OFF_YP + (b * 72 + c) * 121 + tid] = r;
    }
}

// ---------------- launch ----------------
extern "C" void kernel_launch(void* const* d_in, const int* in_sizes, int n_in,
                              void* d_out, int out_size) {
    const float* x   = (const float*)d_in[0];
    const float* w1  = (const float*)d_in[1];
    const float* lna = (const float*)d_in[3];
    const float* lnb = (const float*)d_in[4];
    const float* w2  = (const float*)d_in[5];
    const float* b2  = (const float*)d_in[6];
    const float* fcw = (const float*)d_in[7];
    const float* fcb = (const float*)d_in[8];
    const float* dw1 = (const float*)d_in[9];
    const float* bng = (const float*)d_in[11];
    const float* bnb = (const float*)d_in[12];
    const float* dw2 = (const float*)d_in[13];
    const float* db2 = (const float*)d_in[14];
    float* out = (float*)d_out;

    const int SMEM_S = (72 * 244 + 24 * 72) * 4;            // 77184
    const int SMEM_E = (4 * 4080 + 512 + 256) * 4;          // 68352
    cudaFuncSetAttribute(s_kernel, cudaFuncAttributeMaxDynamicSharedMemorySize, SMEM_S);
    cudaFuncSetAttribute(encode_k, cudaFuncAttributeMaxDynamicSharedMemorySize, SMEM_E);

    prep_k<<<128, 256>>>(w2);
    s_kernel<<<dim3(121, 16), 256, SMEM_S>>>(x, w1);
    prefix_k<<<384, 256>>>();
    encode_k<<<960, 128, SMEM_E>>>(lna, lnb, b2, fcw, fcb, out);
    overlap_k<<<128, 360>>>(out);
    dec1_k<<<dim3(16, 24), 256>>>(dw1);
    bnstat_k<<<24, 256>>>();
    bnapply_k<<<540, 256>>>(bng, bnb);
    dec2_k<<<dim3(16, 72), 256>>>(dw2, db2, out);
}